// round 4
// baseline (speedup 1.0000x reference)
#include <cuda_runtime.h>
#include <cuda_bf16.h>
#include <cstdint>
#include <math.h>

// Problem constants
#define B_   4
#define NA_  64
#define T_   128
#define D_   128
#define H_   8
#define DH_  16
#define L_   3
#define DFF_ 512
#define E_   65536
#define NN_  (T_ * NA_)        // 8192
#define R_   (B_ * NA_ * T_)   // 32768 rows
#define EPSV 1e-5f

// ---------------- scratch (device globals; no allocation allowed) ----------------
__device__ __align__(256) float d_x   [R_ * D_];
__device__ __align__(256) float d_oute[R_ * D_];
__device__ __align__(256) float d_q   [R_ * D_];
__device__ __align__(256) float d_k   [R_ * D_];
__device__ __align__(256) float d_v   [R_ * D_];
__device__ __align__(256) float d_h1  [R_ * D_];
__device__ __align__(256) float d_tmp [R_ * D_];
__device__ __align__(256) float d_ff  [R_ * DFF_];
__device__ __align__(256) float d_s   [B_ * NN_];
__device__ __align__(256) float d_g   [B_ * NN_];
__device__ double d_stats[2];

// ---------------- bf16 split helpers ---------------------------------------------
__device__ __forceinline__ void split2(float x0, float x1, uint32_t& h, uint32_t& l) {
    __nv_bfloat16 h0 = __float2bfloat16_rn(x0);
    __nv_bfloat16 h1 = __float2bfloat16_rn(x1);
    __nv_bfloat16 l0 = __float2bfloat16_rn(x0 - __bfloat162float(h0));
    __nv_bfloat16 l1 = __float2bfloat16_rn(x1 - __bfloat162float(h1));
    h = (uint32_t)__bfloat16_as_ushort(h0) | ((uint32_t)__bfloat16_as_ushort(h1) << 16);
    l = (uint32_t)__bfloat16_as_ushort(l0) | ((uint32_t)__bfloat16_as_ushort(l1) << 16);
}

__device__ __forceinline__ void mma_bf16(float* c, const uint32_t* a,
                                         uint32_t b0, uint32_t b1) {
    asm volatile(
        "mma.sync.aligned.m16n8k16.row.col.f32.bf16.bf16.f32 "
        "{%0,%1,%2,%3}, {%4,%5,%6,%7}, {%8,%9}, {%0,%1,%2,%3};"
        : "+f"(c[0]), "+f"(c[1]), "+f"(c[2]), "+f"(c[3])
        : "r"(a[0]), "r"(a[1]), "r"(a[2]), "r"(a[3]), "r"(b0), "r"(b1));
}

// ---------------- tensor-core split-bf16 GEMM: C = A(MxK) @ W(KxN) + bias --------
// CTA tile 128x128, BK=32, 256 threads (8 warps, each 32m x 64n). 2 CTAs/SM.
#define SAB 40   // bf16 elements per smem row (stride); conflict-free for frag loads

__global__ void __launch_bounds__(256, 2)
bf16_gemm_kernel(const float* __restrict__ A, const float* __restrict__ W,
                 const float* __restrict__ bias, float* __restrict__ C,
                 int K, int N, int relu)
{
    __shared__ uint16_t Ah[128 * SAB];
    __shared__ uint16_t Al[128 * SAB];
    __shared__ uint16_t Bh[128 * SAB];
    __shared__ uint16_t Bl[128 * SAB];

    int tid  = threadIdx.x;
    int wid  = tid >> 5;
    int lane = tid & 31;
    int g    = lane >> 2;    // 0..7
    int tg   = lane & 3;     // 0..3
    int warp_m = wid & 3;    // 32-row band
    int warp_n = wid >> 2;   // 64-col band
    int bm0 = blockIdx.y * 128;
    int bn0 = blockIdx.x * 128;

    float acc[2][8][4];
#pragma unroll
    for (int mt = 0; mt < 2; mt++)
#pragma unroll
        for (int nt = 0; nt < 8; nt++)
#pragma unroll
            for (int j = 0; j < 4; j++) acc[mt][nt][j] = 0.0f;

    for (int kc = 0; kc < K; kc += 32) {
        // ---- fill A tile (128 rows x 32 k), split hi/lo, row-major stride SAB ----
#pragma unroll
        for (int i = 0; i < 4; i++) {
            int li = i * 256 + tid;
            int r = li >> 3;
            int c = (li & 7) * 4;
            float4 a4 = *(const float4*)(A + (size_t)(bm0 + r) * K + kc + c);
            uint32_t h0, l0, h1, l1;
            split2(a4.x, a4.y, h0, l0);
            split2(a4.z, a4.w, h1, l1);
            *(uint2*)&Ah[r * SAB + c] = make_uint2(h0, h1);
            *(uint2*)&Al[r * SAB + c] = make_uint2(l0, l1);
        }
        // ---- fill B tile transposed: Bs[n][k], n=0..127, k=0..31 -----------------
#pragma unroll
        for (int i = 0; i < 4; i++) {
            int li = i * 256 + tid;
            int k = li >> 5;
            int n4 = (li & 31) * 4;
            float4 b4 = *(const float4*)(W + (size_t)(kc + k) * N + bn0 + n4);
            float v[4] = {b4.x, b4.y, b4.z, b4.w};
#pragma unroll
            for (int j = 0; j < 4; j++) {
                __nv_bfloat16 h = __float2bfloat16_rn(v[j]);
                __nv_bfloat16 lo = __float2bfloat16_rn(v[j] - __bfloat162float(h));
                Bh[(n4 + j) * SAB + k] = __bfloat16_as_ushort(h);
                Bl[(n4 + j) * SAB + k] = __bfloat16_as_ushort(lo);
            }
        }
        __syncthreads();

#pragma unroll
        for (int ks = 0; ks < 2; ks++) {
            int c0 = ks * 16 + 2 * tg;
            uint32_t ah[2][4], al[2][4];
#pragma unroll
            for (int mt = 0; mt < 2; mt++) {
                int r0 = warp_m * 32 + mt * 16 + g;
                ah[mt][0] = *(const uint32_t*)&Ah[r0 * SAB + c0];
                ah[mt][1] = *(const uint32_t*)&Ah[(r0 + 8) * SAB + c0];
                ah[mt][2] = *(const uint32_t*)&Ah[r0 * SAB + c0 + 8];
                ah[mt][3] = *(const uint32_t*)&Ah[(r0 + 8) * SAB + c0 + 8];
                al[mt][0] = *(const uint32_t*)&Al[r0 * SAB + c0];
                al[mt][1] = *(const uint32_t*)&Al[(r0 + 8) * SAB + c0];
                al[mt][2] = *(const uint32_t*)&Al[r0 * SAB + c0 + 8];
                al[mt][3] = *(const uint32_t*)&Al[(r0 + 8) * SAB + c0 + 8];
            }
#pragma unroll
            for (int nt = 0; nt < 8; nt++) {
                int n0 = (warp_n * 64 + nt * 8 + g) * SAB + c0;
                uint32_t bh0 = *(const uint32_t*)&Bh[n0];
                uint32_t bh1 = *(const uint32_t*)&Bh[n0 + 8];
                uint32_t bl0 = *(const uint32_t*)&Bl[n0];
                uint32_t bl1 = *(const uint32_t*)&Bl[n0 + 8];
#pragma unroll
                for (int mt = 0; mt < 2; mt++) {
                    mma_bf16(acc[mt][nt], ah[mt], bh0, bh1);
                    mma_bf16(acc[mt][nt], ah[mt], bl0, bl1);
                    mma_bf16(acc[mt][nt], al[mt], bh0, bh1);
                }
            }
        }
        __syncthreads();
    }

    // ---- epilogue: bias (+ReLU), direct global stores ----
#pragma unroll
    for (int mt = 0; mt < 2; mt++) {
        int r0 = bm0 + warp_m * 32 + mt * 16 + g;
#pragma unroll
        for (int nt = 0; nt < 8; nt++) {
            int c0 = bn0 + warp_n * 64 + nt * 8 + tg * 2;
            float b0 = bias[c0], b1 = bias[c0 + 1];
            float v0 = acc[mt][nt][0] + b0;
            float v1 = acc[mt][nt][1] + b1;
            float v2 = acc[mt][nt][2] + b0;
            float v3 = acc[mt][nt][3] + b1;
            if (relu) {
                v0 = fmaxf(v0, 0.0f); v1 = fmaxf(v1, 0.0f);
                v2 = fmaxf(v2, 0.0f); v3 = fmaxf(v3, 0.0f);
            }
            *(float2*)(C + (size_t)r0 * N + c0)       = make_float2(v0, v1);
            *(float2*)(C + (size_t)(r0 + 8) * N + c0) = make_float2(v2, v3);
        }
    }
}

// ---------------- kernel 1: hist projection + positional encoding ----------------
__global__ void hist_pe_kernel(const float* __restrict__ feat,
                               const float* __restrict__ hw,
                               const float* __restrict__ hb)
{
    int idx = blockIdx.x * blockDim.x + threadIdx.x;
    if (idx >= R_ * D_) return;
    int row = idx >> 7;
    int d   = idx & 127;
    int t   = row & (T_ - 1);
    const float* f = feat + (size_t)row * 3;
    float xv = fmaf(f[0], hw[d],
               fmaf(f[1], hw[D_ + d],
               fmaf(f[2], hw[2 * D_ + d], hb[d])));
    d_x[idx] = xv;
    int j2 = d & ~1;
    float ang = (float)t * __expf(-9.210340371976184f * (float)j2 / 128.0f);
    float pe = (d & 1) ? cosf(ang) : sinf(ang);
    d_oute[idx] = xv + pe;
}

// ---------------- attention per (b,n,h) block; writes O in-place over Q ---------
__global__ __launch_bounds__(128)
void attn_kernel(float* __restrict__ q, const float* __restrict__ k,
                 const float* __restrict__ v)
{
    int blk = blockIdx.x;
    int h   = blk % H_;
    int bn  = blk / H_;
    const float* kb = k + (size_t)bn * T_ * D_;
    const float* vb = v + (size_t)bn * T_ * D_;

    __shared__ float Ks[T_][DH_];
    __shared__ float Vs[T_][DH_];
    int tid = threadIdx.x;
    for (int i = tid; i < T_ * DH_; i += 128) {
        int r = i >> 4, c = i & 15;
        Ks[r][c] = kb[(size_t)r * D_ + h * DH_ + c];
        Vs[r][c] = vb[(size_t)r * D_ + h * DH_ + c];
    }
    __syncthreads();

    float* qrow = q + (size_t)bn * T_ * D_ + (size_t)tid * D_ + h * DH_;
    const float scale = 0.25f;
    float qr[DH_];
#pragma unroll
    for (int d = 0; d < DH_; d++) qr[d] = qrow[d] * scale;

    float m = -INFINITY, l = 0.0f;
    float acc[DH_];
#pragma unroll
    for (int d = 0; d < DH_; d++) acc[d] = 0.0f;

    for (int kk = 0; kk < T_; kk++) {
        float sc = 0.0f;
#pragma unroll
        for (int d = 0; d < DH_; d++) sc = fmaf(qr[d], Ks[kk][d], sc);
        float mn = fmaxf(m, sc);
        float corr = __expf(m - mn);
        float p = __expf(sc - mn);
        l = l * corr + p;
#pragma unroll
        for (int d = 0; d < DH_; d++) acc[d] = fmaf(acc[d], corr, p * Vs[kk][d]);
        m = mn;
    }
    float inv = 1.0f / l;
#pragma unroll
    for (int d = 0; d < DH_; d++) qrow[d] = acc[d] * inv;
}

// ---------------- out = LayerNorm(a + c) * g + b, one warp per row --------------
__global__ void add_ln_kernel(const float* __restrict__ a, const float* __restrict__ c,
                              const float* __restrict__ g, const float* __restrict__ bb,
                              float* __restrict__ out)
{
    int warp = (blockIdx.x * blockDim.x + threadIdx.x) >> 5;
    int lane = threadIdx.x & 31;
    if (warp >= R_) return;
    size_t base = (size_t)warp * D_ + lane * 4;
    float4 av = *(const float4*)(a + base);
    float4 cv = *(const float4*)(c + base);
    float h0 = av.x + cv.x, h1 = av.y + cv.y, h2 = av.z + cv.z, h3 = av.w + cv.w;
    float sum = h0 + h1 + h2 + h3;
#pragma unroll
    for (int o = 16; o; o >>= 1) sum += __shfl_xor_sync(0xffffffffu, sum, o);
    float mu = sum * (1.0f / 128.0f);
    float e0 = h0 - mu, e1 = h1 - mu, e2 = h2 - mu, e3 = h3 - mu;
    float vs = e0 * e0 + e1 * e1 + e2 * e2 + e3 * e3;
#pragma unroll
    for (int o = 16; o; o >>= 1) vs += __shfl_xor_sync(0xffffffffu, vs, o);
    float inv = rsqrtf(vs * (1.0f / 128.0f) + EPSV);
    float4 gv = *(const float4*)(g + lane * 4);
    float4 bv = *(const float4*)(bb + lane * 4);
    float4 r;
    r.x = e0 * inv * gv.x + bv.x;
    r.y = e1 * inv * gv.y + bv.y;
    r.z = e2 * inv * gv.z + bv.z;
    r.w = e3 * inv * gv.w + bv.w;
    *(float4*)(out + base) = r;
}

// ---------------- s[b, t*NA+n] = dot(out_e[b,n,t,:], x[b,n,t,:]) ----------------
__global__ void sdot_kernel()
{
    int warp = (blockIdx.x * blockDim.x + threadIdx.x) >> 5;
    int lane = threadIdx.x & 31;
    if (warp >= R_) return;
    size_t base = (size_t)warp * D_ + lane * 4;
    float4 w4 = *(const float4*)(d_oute + base);
    float4 x4 = *(const float4*)(d_x + base);
    float dt = w4.x * x4.x + w4.y * x4.y + w4.z * x4.z + w4.w * x4.w;
#pragma unroll
    for (int o = 16; o; o >>= 1) dt += __shfl_xor_sync(0xffffffffu, dt, o);
    if (lane == 0) {
        int b = warp / (NA_ * T_);
        int rem = warp % (NA_ * T_);
        int n = rem / T_;
        int t = rem % T_;
        d_s[b * NN_ + t * NA_ + n] = dt;
    }
}

// ---------------- zero accumulators ---------------------------------------------
__global__ void zero_kernel()
{
    int i = blockIdx.x * blockDim.x + threadIdx.x;
    if (i < B_ * NN_) d_g[i] = 0.0f;
    if (i < 2) d_stats[i] = 0.0;
}

// ---------------- edge aggregation ----------------------------------------------
__global__ void edge_kernel(const int* __restrict__ ei, const float* __restrict__ ew)
{
    int gid = blockIdx.x * blockDim.x + threadIdx.x;
    if (gid >= B_ * E_) return;
    int b = gid / E_;
    int e = gid % E_;
    const int* eb = ei + (size_t)b * 2 * E_;
    int src = eb[e];
    int dst = eb[E_ + e];
    atomicAdd(&d_g[b * NN_ + dst], ew[(size_t)b * E_ + e] * d_s[b * NN_ + src]);
}

// ---------------- global batchnorm stats (double precision) ---------------------
__global__ void bnstats_kernel()
{
    double s = 0.0, sq = 0.0;
    for (int i = blockIdx.x * blockDim.x + threadIdx.x; i < B_ * NN_;
         i += gridDim.x * blockDim.x) {
        double v = (double)d_g[i];
        s += v; sq += v * v;
    }
#pragma unroll
    for (int o = 16; o; o >>= 1) {
        s  += __shfl_xor_sync(0xffffffffu, s, o);
        sq += __shfl_xor_sync(0xffffffffu, sq, o);
    }
    if ((threadIdx.x & 31) == 0) {
        atomicAdd(&d_stats[0], s);
        atomicAdd(&d_stats[1], sq);
    }
}

// ---------------- final outer product -------------------------------------------
__global__ void final_kernel(const float* __restrict__ bng, const float* __restrict__ bnb,
                             const float* __restrict__ lw, const float* __restrict__ lb,
                             float* __restrict__ out)
{
    int idx = blockIdx.x * blockDim.x + threadIdx.x;
    if (idx >= R_ * D_) return;
    int d   = idx & 127;
    int row = idx >> 7;
    int t   = row & 127;
    int bn  = row >> 7;
    int b   = bn >> 6;
    int n   = bn & 63;
    double mu  = d_stats[0] * (1.0 / 32768.0);
    double var = d_stats[1] * (1.0 / 32768.0) - mu * mu;
    float inv = rsqrtf((float)var + EPSV);
    float gval = d_g[b * NN_ + t * NA_ + n];
    float ghat = ((gval - (float)mu) * inv) * bng[0] + bnb[0];
    out[idx] = ghat * lw[d] + lb[d];
}

// ---------------- launcher -------------------------------------------------------
static inline void run_gemm(const float* A, const float* W, const float* bias,
                            float* C, int M, int N, int K, int relu)
{
    dim3 grid(N / 128, M / 128);
    bf16_gemm_kernel<<<grid, 256>>>(A, W, bias, C, K, N, relu);
}

extern "C" void kernel_launch(void* const* d_in, const int* in_sizes, int n_in,
                              void* d_out, int out_size)
{
    const float* feat    = (const float*)d_in[0];
    const int*   eindex  = (const int*)  d_in[1];
    const float* eweight = (const float*)d_in[2];
    const float* hist_w  = (const float*)d_in[3];
    const float* hist_b  = (const float*)d_in[4];
    const float* wq      = (const float*)d_in[5];
    const float* bq      = (const float*)d_in[6];
    const float* wk      = (const float*)d_in[7];
    const float* bk      = (const float*)d_in[8];
    const float* wv      = (const float*)d_in[9];
    const float* bv      = (const float*)d_in[10];
    const float* wo      = (const float*)d_in[11];
    const float* bo      = (const float*)d_in[12];
    const float* ln1g    = (const float*)d_in[13];
    const float* ln1b    = (const float*)d_in[14];
    const float* fw1     = (const float*)d_in[15];
    const float* fb1     = (const float*)d_in[16];
    const float* fw2     = (const float*)d_in[17];
    const float* fb2     = (const float*)d_in[18];
    const float* ln2g    = (const float*)d_in[19];
    const float* ln2b    = (const float*)d_in[20];
    const float* bng     = (const float*)d_in[21];
    const float* bnb     = (const float*)d_in[22];
    const float* linw    = (const float*)d_in[23];
    const float* linb    = (const float*)d_in[24];
    float* out = (float*)d_out;

    float* px    = nullptr; cudaGetSymbolAddress((void**)&px,    d_x);
    float* poute = nullptr; cudaGetSymbolAddress((void**)&poute, d_oute);
    float* pq    = nullptr; cudaGetSymbolAddress((void**)&pq,    d_q);
    float* pk    = nullptr; cudaGetSymbolAddress((void**)&pk,    d_k);
    float* pv    = nullptr; cudaGetSymbolAddress((void**)&pv,    d_v);
    float* ph1   = nullptr; cudaGetSymbolAddress((void**)&ph1,   d_h1);
    float* ptmp  = nullptr; cudaGetSymbolAddress((void**)&ptmp,  d_tmp);
    float* pff   = nullptr; cudaGetSymbolAddress((void**)&pff,   d_ff);

    const int TPB = 256;

    // 1. x + positional encoding
    hist_pe_kernel<<<(R_ * D_ + TPB - 1) / TPB, TPB>>>(feat, hist_w, hist_b);

    // 2. transformer layers
    for (int l = 0; l < L_; l++) {
        const float* wql = wq + (size_t)l * D_ * D_;
        const float* wkl = wk + (size_t)l * D_ * D_;
        const float* wvl = wv + (size_t)l * D_ * D_;
        const float* wol = wo + (size_t)l * D_ * D_;
        run_gemm(poute, wql, bq + l * D_, pq, R_, D_, D_, 0);
        run_gemm(poute, wkl, bk + l * D_, pk, R_, D_, D_, 0);
        run_gemm(poute, wvl, bv + l * D_, pv, R_, D_, D_, 0);
        attn_kernel<<<B_ * NA_ * H_, 128>>>(pq, pk, pv);
        run_gemm(pq, wol, bo + l * D_, ptmp, R_, D_, D_, 0);
        add_ln_kernel<<<(R_ * 32 + TPB - 1) / TPB, TPB>>>(poute, ptmp,
                                                          ln1g + l * D_, ln1b + l * D_, ph1);
        run_gemm(ph1, fw1 + (size_t)l * D_ * DFF_, fb1 + l * DFF_, pff, R_, DFF_, D_, 1);
        run_gemm(pff, fw2 + (size_t)l * DFF_ * D_, fb2 + l * D_, ptmp, R_, D_, DFF_, 0);
        add_ln_kernel<<<(R_ * 32 + TPB - 1) / TPB, TPB>>>(ph1, ptmp,
                                                          ln2g + l * D_, ln2b + l * D_, poute);
    }

    // 3. scoring dot products
    sdot_kernel<<<(R_ * 32 + TPB - 1) / TPB, TPB>>>();

    // 4. edge aggregation
    zero_kernel<<<(B_ * NN_ + TPB - 1) / TPB, TPB>>>();
    edge_kernel<<<(B_ * E_ + TPB - 1) / TPB, TPB>>>(eindex, eweight);

    // 5. global batchnorm stats + final outer product
    bnstats_kernel<<<64, TPB>>>();
    final_kernel<<<(R_ * D_ + TPB - 1) / TPB, TPB>>>(bng, bnb, linw, linb, out);
}

// round 5
// speedup vs baseline: 1.3089x; 1.3089x over previous
#include <cuda_runtime.h>
#include <cuda_bf16.h>
#include <cstdint>
#include <math.h>

// Problem constants
#define B_   4
#define NA_  64
#define T_   128
#define D_   128
#define H_   8
#define DH_  16
#define L_   3
#define DFF_ 512
#define E_   65536
#define NN_  (T_ * NA_)        // 8192
#define R_   (B_ * NA_ * T_)   // 32768 rows
#define EPSV 1e-5f

// ---------------- scratch (device globals; no allocation allowed) ----------------
__device__ __align__(256) float d_x   [R_ * D_];
__device__ __align__(256) float d_oute[R_ * D_];
__device__ __align__(256) float d_q   [R_ * D_];
__device__ __align__(256) float d_k   [R_ * D_];
__device__ __align__(256) float d_v   [R_ * D_];
__device__ __align__(256) float d_h1  [R_ * D_];
__device__ __align__(256) float d_tmp [R_ * D_];
__device__ __align__(256) float d_s   [B_ * NN_];
__device__ __align__(256) float d_g   [B_ * NN_];
__device__ double d_stats[2];

// bf16 split activations (hi / lo)
__device__ __align__(256) __nv_bfloat16 d_oute_h[R_ * D_];
__device__ __align__(256) __nv_bfloat16 d_oute_l[R_ * D_];
__device__ __align__(256) __nv_bfloat16 d_qh[R_ * D_];
__device__ __align__(256) __nv_bfloat16 d_ql[R_ * D_];
__device__ __align__(256) __nv_bfloat16 d_h1h[R_ * D_];
__device__ __align__(256) __nv_bfloat16 d_h1l[R_ * D_];
__device__ __align__(256) __nv_bfloat16 d_ffh[R_ * DFF_];
__device__ __align__(256) __nv_bfloat16 d_ffl[R_ * DFF_];

// bf16 split transposed weights: [N][K] layout
// regions (elems): sq: type*49152 + l*16384  (4 types: q,k,v,o)
//                  f1: 196608 + l*65536  ([512][128])
//                  f2: 393216 + l*65536  ([128][512])
#define W_TOT 589824
__device__ __align__(256) __nv_bfloat16 d_wh[W_TOT];
__device__ __align__(256) __nv_bfloat16 d_wl[W_TOT];

// ---------------- helpers --------------------------------------------------------
__device__ __forceinline__ uint32_t smem_u32(const void* p) {
    uint32_t a;
    asm("{ .reg .u64 t; cvta.to.shared.u64 t, %1; cvt.u32.u64 %0, t; }" : "=r"(a) : "l"(p));
    return a;
}
__device__ __forceinline__ void cp16(uint32_t saddr, const void* gptr) {
    asm volatile("cp.async.cg.shared.global [%0], [%1], 16;" :: "r"(saddr), "l"(gptr));
}
#define CP_COMMIT() asm volatile("cp.async.commit_group;" ::: "memory")
#define CP_WAIT(n)  asm volatile("cp.async.wait_group %0;" :: "n"(n) : "memory")

__device__ __forceinline__ void bf16split(float v, __nv_bfloat16& h, __nv_bfloat16& l) {
    h = __float2bfloat16_rn(v);
    l = __float2bfloat16_rn(v - __bfloat162float(h));
}

__device__ __forceinline__ void mma_bf16(float* c, const uint32_t* a,
                                         uint32_t b0, uint32_t b1) {
    asm volatile(
        "mma.sync.aligned.m16n8k16.row.col.f32.bf16.bf16.f32 "
        "{%0,%1,%2,%3}, {%4,%5,%6,%7}, {%8,%9}, {%0,%1,%2,%3};"
        : "+f"(c[0]), "+f"(c[1]), "+f"(c[2]), "+f"(c[3])
        : "r"(a[0]), "r"(a[1]), "r"(a[2]), "r"(a[3]), "r"(b0), "r"(b1));
}

// ---------------- split-bf16 GEMM with cp.async double buffering ------------------
// C = A @ B^T(stored [N][K]) + bias.  A,B pre-split bf16 hi/lo in global.
// CTA tile 128x128, BK=32, 256 threads (8 warps, 32m x 64n each).
#define SAB 40                       // bf16 elems per smem row (80B: 16B-mult, bank-safe)
#define ARR_ELEMS (128 * SAB)        // per array per stage
#define STAGE_ELEMS (4 * ARR_ELEMS)
#define GEMM_SMEM (2 * STAGE_ELEMS * 2)   // bytes = 81920

__global__ void __launch_bounds__(256, 2)
split_gemm_kernel(const __nv_bfloat16* __restrict__ Ahg, const __nv_bfloat16* __restrict__ Alg,
                  const __nv_bfloat16* __restrict__ Bhg, const __nv_bfloat16* __restrict__ Blg,
                  const float* __restrict__ bias, float* __restrict__ Cf,
                  __nv_bfloat16* __restrict__ Ch, __nv_bfloat16* __restrict__ Cl,
                  int K, int N, int relu)
{
    extern __shared__ uint16_t smbuf[];   // [2][4][128*SAB]

    int tid  = threadIdx.x;
    int wid  = tid >> 5;
    int lane = tid & 31;
    int g    = lane >> 2;
    int tg   = lane & 3;
    int warp_m = wid & 3;
    int warp_n = wid >> 2;
    int bm0 = blockIdx.y * 128;
    int bn0 = blockIdx.x * 128;

    const __nv_bfloat16* gbase[4];
    gbase[0] = Ahg + (size_t)bm0 * K;
    gbase[1] = Alg + (size_t)bm0 * K;
    gbase[2] = Bhg + (size_t)bn0 * K;
    gbase[3] = Blg + (size_t)bn0 * K;

    int lrow = tid >> 2;         // 0..63
    int lch  = tid & 3;          // 16B chunk within 64B row-chunk

    float acc[2][8][4];
#pragma unroll
    for (int mt = 0; mt < 2; mt++)
#pragma unroll
        for (int nt = 0; nt < 8; nt++)
#pragma unroll
            for (int j = 0; j < 4; j++) acc[mt][nt][j] = 0.0f;

    int nch = K >> 5;

    // prologue: load stage 0
    {
        uint16_t* st = smbuf;
#pragma unroll
        for (int arr = 0; arr < 4; arr++) {
            uint16_t* da = st + arr * ARR_ELEMS;
#pragma unroll
            for (int it = 0; it < 2; it++) {
                int row = lrow + it * 64;
                cp16(smem_u32(da + row * SAB + lch * 8),
                     gbase[arr] + (size_t)row * K + lch * 8);
            }
        }
    }
    CP_COMMIT();

    for (int kc = 0; kc < nch; kc++) {
        if (kc + 1 < nch) {
            uint16_t* st = smbuf + ((kc + 1) & 1) * STAGE_ELEMS;
            int koff = (kc + 1) * 32;
#pragma unroll
            for (int arr = 0; arr < 4; arr++) {
                uint16_t* da = st + arr * ARR_ELEMS;
#pragma unroll
                for (int it = 0; it < 2; it++) {
                    int row = lrow + it * 64;
                    cp16(smem_u32(da + row * SAB + lch * 8),
                         gbase[arr] + (size_t)row * K + koff + lch * 8);
                }
            }
            CP_COMMIT();
            CP_WAIT(1);
        } else {
            CP_WAIT(0);
        }
        __syncthreads();

        uint16_t* st = smbuf + (kc & 1) * STAGE_ELEMS;
        uint16_t* Ah = st;
        uint16_t* Al = st + ARR_ELEMS;
        uint16_t* Bh = st + 2 * ARR_ELEMS;
        uint16_t* Bl = st + 3 * ARR_ELEMS;

#pragma unroll
        for (int ks = 0; ks < 2; ks++) {
            int c0 = ks * 16 + 2 * tg;
            uint32_t ah[2][4], al[2][4];
#pragma unroll
            for (int mt = 0; mt < 2; mt++) {
                int r0 = warp_m * 32 + mt * 16 + g;
                ah[mt][0] = *(const uint32_t*)&Ah[r0 * SAB + c0];
                ah[mt][1] = *(const uint32_t*)&Ah[(r0 + 8) * SAB + c0];
                ah[mt][2] = *(const uint32_t*)&Ah[r0 * SAB + c0 + 8];
                ah[mt][3] = *(const uint32_t*)&Ah[(r0 + 8) * SAB + c0 + 8];
                al[mt][0] = *(const uint32_t*)&Al[r0 * SAB + c0];
                al[mt][1] = *(const uint32_t*)&Al[(r0 + 8) * SAB + c0];
                al[mt][2] = *(const uint32_t*)&Al[r0 * SAB + c0 + 8];
                al[mt][3] = *(const uint32_t*)&Al[(r0 + 8) * SAB + c0 + 8];
            }
#pragma unroll
            for (int nt = 0; nt < 8; nt++) {
                int n0 = (warp_n * 64 + nt * 8 + g) * SAB + c0;
                uint32_t bh0 = *(const uint32_t*)&Bh[n0];
                uint32_t bh1 = *(const uint32_t*)&Bh[n0 + 8];
                uint32_t bl0 = *(const uint32_t*)&Bl[n0];
                uint32_t bl1 = *(const uint32_t*)&Bl[n0 + 8];
#pragma unroll
                for (int mt = 0; mt < 2; mt++) {
                    mma_bf16(acc[mt][nt], ah[mt], bh0, bh1);
                    mma_bf16(acc[mt][nt], ah[mt], bl0, bl1);
                    mma_bf16(acc[mt][nt], al[mt], bh0, bh1);
                }
            }
        }
        __syncthreads();
    }

    // ---- epilogue ----
#pragma unroll
    for (int mt = 0; mt < 2; mt++) {
        int r0 = bm0 + warp_m * 32 + mt * 16 + g;
#pragma unroll
        for (int nt = 0; nt < 8; nt++) {
            int c0 = bn0 + warp_n * 64 + nt * 8 + tg * 2;
            float b0 = bias[c0], b1 = bias[c0 + 1];
            float v0 = acc[mt][nt][0] + b0;
            float v1 = acc[mt][nt][1] + b1;
            float v2 = acc[mt][nt][2] + b0;
            float v3 = acc[mt][nt][3] + b1;
            if (relu) {
                v0 = fmaxf(v0, 0.0f); v1 = fmaxf(v1, 0.0f);
                v2 = fmaxf(v2, 0.0f); v3 = fmaxf(v3, 0.0f);
            }
            if (Cf) {
                *(float2*)(Cf + (size_t)r0 * N + c0)       = make_float2(v0, v1);
                *(float2*)(Cf + (size_t)(r0 + 8) * N + c0) = make_float2(v2, v3);
            }
            if (Ch) {
                __nv_bfloat16 h, l;
                size_t o0 = (size_t)r0 * N + c0;
                size_t o1 = (size_t)(r0 + 8) * N + c0;
                bf16split(v0, h, l); Ch[o0]     = h; Cl[o0]     = l;
                bf16split(v1, h, l); Ch[o0 + 1] = h; Cl[o0 + 1] = l;
                bf16split(v2, h, l); Ch[o1]     = h; Cl[o1]     = l;
                bf16split(v3, h, l); Ch[o1 + 1] = h; Cl[o1 + 1] = l;
            }
        }
    }
}

// ---------------- weight split+transpose kernels ---------------------------------
__global__ void wsplit_sq_kernel(const float* __restrict__ wq, const float* __restrict__ wk,
                                 const float* __restrict__ wv, const float* __restrict__ wo)
{
    int idx = blockIdx.x * blockDim.x + threadIdx.x;
    if (idx >= L_ * 4 * 16384) return;
    int type = idx / (L_ * 16384);
    int rem  = idx % (L_ * 16384);
    int l    = rem / 16384;
    int kn   = rem % 16384;
    int k = kn >> 7, n = kn & 127;
    const float* src = (type == 0) ? wq : (type == 1) ? wk : (type == 2) ? wv : wo;
    float v = src[l * 16384 + k * 128 + n];
    __nv_bfloat16 h, lo;
    bf16split(v, h, lo);
    int off = type * 49152 + l * 16384 + n * 128 + k;
    d_wh[off] = h; d_wl[off] = lo;
}

__global__ void wsplit_ff_kernel(const float* __restrict__ f1, const float* __restrict__ f2)
{
    int idx = blockIdx.x * blockDim.x + threadIdx.x;
    if (idx >= 2 * L_ * 65536) return;
    float v; int off;
    if (idx < L_ * 65536) {                  // f1: [l][k<128][n<512] -> [l][n][k]
        int l = idx / 65536, kn = idx % 65536;
        int k = kn >> 9, n = kn & 511;
        v = f1[l * 65536 + k * 512 + n];
        off = 196608 + l * 65536 + n * 128 + k;
    } else {                                 // f2: [l][k<512][n<128] -> [l][n][k]
        int j = idx - L_ * 65536;
        int l = j / 65536, kn = j % 65536;
        int k = kn >> 7, n = kn & 127;
        v = f2[l * 65536 + k * 128 + n];
        off = 393216 + l * 65536 + n * 512 + k;
    }
    __nv_bfloat16 h, lo;
    bf16split(v, h, lo);
    d_wh[off] = h; d_wl[off] = lo;
}

// ---------------- kernel 1: hist projection + positional encoding ----------------
__global__ void hist_pe_kernel(const float* __restrict__ feat,
                               const float* __restrict__ hw,
                               const float* __restrict__ hb)
{
    int idx = blockIdx.x * blockDim.x + threadIdx.x;
    if (idx >= R_ * D_) return;
    int row = idx >> 7;
    int d   = idx & 127;
    int t   = row & (T_ - 1);
    const float* f = feat + (size_t)row * 3;
    float xv = fmaf(f[0], hw[d],
               fmaf(f[1], hw[D_ + d],
               fmaf(f[2], hw[2 * D_ + d], hb[d])));
    d_x[idx] = xv;
    int j2 = d & ~1;
    float ang = (float)t * __expf(-9.210340371976184f * (float)j2 / 128.0f);
    float pe = (d & 1) ? cosf(ang) : sinf(ang);
    float oe = xv + pe;
    d_oute[idx] = oe;
    __nv_bfloat16 h, l;
    bf16split(oe, h, l);
    d_oute_h[idx] = h; d_oute_l[idx] = l;
}

// ---------------- attention per (b,n,h) block; writes split O to d_qh/d_ql -------
__global__ __launch_bounds__(128)
void attn_kernel(const float* __restrict__ q, const float* __restrict__ k,
                 const float* __restrict__ v)
{
    int blk = blockIdx.x;
    int h   = blk % H_;
    int bn  = blk / H_;
    const float* kb = k + (size_t)bn * T_ * D_;
    const float* vb = v + (size_t)bn * T_ * D_;

    __shared__ float Ks[T_][DH_];
    __shared__ float Vs[T_][DH_];
    int tid = threadIdx.x;
    for (int i = tid; i < T_ * DH_; i += 128) {
        int r = i >> 4, c = i & 15;
        Ks[r][c] = kb[(size_t)r * D_ + h * DH_ + c];
        Vs[r][c] = vb[(size_t)r * D_ + h * DH_ + c];
    }
    __syncthreads();

    size_t rowoff = (size_t)bn * T_ * D_ + (size_t)tid * D_ + h * DH_;
    const float* qrow = q + rowoff;
    const float scale = 0.25f;
    float qr[DH_];
#pragma unroll
    for (int d = 0; d < DH_; d++) qr[d] = qrow[d] * scale;

    float m = -INFINITY, l = 0.0f;
    float acc[DH_];
#pragma unroll
    for (int d = 0; d < DH_; d++) acc[d] = 0.0f;

    for (int kk = 0; kk < T_; kk++) {
        float sc = 0.0f;
#pragma unroll
        for (int d = 0; d < DH_; d++) sc = fmaf(qr[d], Ks[kk][d], sc);
        float mn = fmaxf(m, sc);
        float corr = __expf(m - mn);
        float p = __expf(sc - mn);
        l = l * corr + p;
#pragma unroll
        for (int d = 0; d < DH_; d++) acc[d] = fmaf(acc[d], corr, p * Vs[kk][d]);
        m = mn;
    }
    float inv = 1.0f / l;
#pragma unroll
    for (int d = 0; d < DH_; d++) {
        float o = acc[d] * inv;
        __nv_bfloat16 hh, ll;
        bf16split(o, hh, ll);
        d_qh[rowoff + d] = hh;
        d_ql[rowoff + d] = ll;
    }
}

// ---------------- out = LayerNorm(a + c) * g + b (fp32 + optional split) --------
__global__ void add_ln_kernel(const float* __restrict__ a, const float* __restrict__ c,
                              const float* __restrict__ g, const float* __restrict__ bb,
                              float* __restrict__ out,
                              __nv_bfloat16* __restrict__ oh, __nv_bfloat16* __restrict__ ol)
{
    int warp = (blockIdx.x * blockDim.x + threadIdx.x) >> 5;
    int lane = threadIdx.x & 31;
    if (warp >= R_) return;
    size_t base = (size_t)warp * D_ + lane * 4;
    float4 av = *(const float4*)(a + base);
    float4 cv = *(const float4*)(c + base);
    float h0 = av.x + cv.x, h1 = av.y + cv.y, h2 = av.z + cv.z, h3 = av.w + cv.w;
    float sum = h0 + h1 + h2 + h3;
#pragma unroll
    for (int o = 16; o; o >>= 1) sum += __shfl_xor_sync(0xffffffffu, sum, o);
    float mu = sum * (1.0f / 128.0f);
    float e0 = h0 - mu, e1 = h1 - mu, e2 = h2 - mu, e3 = h3 - mu;
    float vs = e0 * e0 + e1 * e1 + e2 * e2 + e3 * e3;
#pragma unroll
    for (int o = 16; o; o >>= 1) vs += __shfl_xor_sync(0xffffffffu, vs, o);
    float inv = rsqrtf(vs * (1.0f / 128.0f) + EPSV);
    float4 gv = *(const float4*)(g + lane * 4);
    float4 bv = *(const float4*)(bb + lane * 4);
    float4 r;
    r.x = e0 * inv * gv.x + bv.x;
    r.y = e1 * inv * gv.y + bv.y;
    r.z = e2 * inv * gv.z + bv.z;
    r.w = e3 * inv * gv.w + bv.w;
    *(float4*)(out + base) = r;
    if (oh) {
        __nv_bfloat16 hh, ll;
        bf16split(r.x, hh, ll); oh[base]     = hh; ol[base]     = ll;
        bf16split(r.y, hh, ll); oh[base + 1] = hh; ol[base + 1] = ll;
        bf16split(r.z, hh, ll); oh[base + 2] = hh; ol[base + 2] = ll;
        bf16split(r.w, hh, ll); oh[base + 3] = hh; ol[base + 3] = ll;
    }
}

// ---------------- s[b, t*NA+n] = dot(out_e[b,n,t,:], x[b,n,t,:]) ----------------
__global__ void sdot_kernel()
{
    int warp = (blockIdx.x * blockDim.x + threadIdx.x) >> 5;
    int lane = threadIdx.x & 31;
    if (warp >= R_) return;
    size_t base = (size_t)warp * D_ + lane * 4;
    float4 w4 = *(const float4*)(d_oute + base);
    float4 x4 = *(const float4*)(d_x + base);
    float dt = w4.x * x4.x + w4.y * x4.y + w4.z * x4.z + w4.w * x4.w;
#pragma unroll
    for (int o = 16; o; o >>= 1) dt += __shfl_xor_sync(0xffffffffu, dt, o);
    if (lane == 0) {
        int b = warp / (NA_ * T_);
        int rem = warp % (NA_ * T_);
        int n = rem / T_;
        int t = rem % T_;
        d_s[b * NN_ + t * NA_ + n] = dt;
    }
}

// ---------------- zero accumulators ---------------------------------------------
__global__ void zero_kernel()
{
    int i = blockIdx.x * blockDim.x + threadIdx.x;
    if (i < B_ * NN_) d_g[i] = 0.0f;
    if (i < 2) d_stats[i] = 0.0;
}

// ---------------- edge aggregation ----------------------------------------------
__global__ void edge_kernel(const int* __restrict__ ei, const float* __restrict__ ew)
{
    int gid = blockIdx.x * blockDim.x + threadIdx.x;
    if (gid >= B_ * E_) return;
    int b = gid / E_;
    int e = gid % E_;
    const int* eb = ei + (size_t)b * 2 * E_;
    int src = eb[e];
    int dst = eb[E_ + e];
    atomicAdd(&d_g[b * NN_ + dst], ew[(size_t)b * E_ + e] * d_s[b * NN_ + src]);
}

// ---------------- global batchnorm stats (double precision) ---------------------
__global__ void bnstats_kernel()
{
    double s = 0.0, sq = 0.0;
    for (int i = blockIdx.x * blockDim.x + threadIdx.x; i < B_ * NN_;
         i += gridDim.x * blockDim.x) {
        double v = (double)d_g[i];
        s += v; sq += v * v;
    }
#pragma unroll
    for (int o = 16; o; o >>= 1) {
        s  += __shfl_xor_sync(0xffffffffu, s, o);
        sq += __shfl_xor_sync(0xffffffffu, sq, o);
    }
    if ((threadIdx.x & 31) == 0) {
        atomicAdd(&d_stats[0], s);
        atomicAdd(&d_stats[1], sq);
    }
}

// ---------------- final outer product -------------------------------------------
__global__ void final_kernel(const float* __restrict__ bng, const float* __restrict__ bnb,
                             const float* __restrict__ lw, const float* __restrict__ lb,
                             float* __restrict__ out)
{
    int idx = blockIdx.x * blockDim.x + threadIdx.x;
    if (idx >= R_ * D_) return;
    int d   = idx & 127;
    int row = idx >> 7;
    int t   = row & 127;
    int bn  = row >> 7;
    int b   = bn >> 6;
    int n   = bn & 63;
    double mu  = d_stats[0] * (1.0 / 32768.0);
    double var = d_stats[1] * (1.0 / 32768.0) - mu * mu;
    float inv = rsqrtf((float)var + EPSV);
    float gval = d_g[b * NN_ + t * NA_ + n];
    float ghat = ((gval - (float)mu) * inv) * bng[0] + bnb[0];
    out[idx] = ghat * lw[d] + lb[d];
}

// ---------------- launcher -------------------------------------------------------
struct Bf16Ptrs {
    __nv_bfloat16 *oute_h, *oute_l, *qh, *ql, *h1h, *h1l, *ffh, *ffl, *wh, *wl;
};

static inline void run_gemm(const __nv_bfloat16* Ah, const __nv_bfloat16* Al,
                            const __nv_bfloat16* Bh, const __nv_bfloat16* Bl,
                            const float* bias, float* Cf,
                            __nv_bfloat16* Ch, __nv_bfloat16* Cl,
                            int M, int N, int K, int relu)
{
    cudaFuncSetAttribute(split_gemm_kernel,
                         cudaFuncAttributeMaxDynamicSharedMemorySize, GEMM_SMEM);
    dim3 grid(N / 128, M / 128);
    split_gemm_kernel<<<grid, 256, GEMM_SMEM>>>(Ah, Al, Bh, Bl, bias, Cf, Ch, Cl, K, N, relu);
}

extern "C" void kernel_launch(void* const* d_in, const int* in_sizes, int n_in,
                              void* d_out, int out_size)
{
    const float* feat    = (const float*)d_in[0];
    const int*   eindex  = (const int*)  d_in[1];
    const float* eweight = (const float*)d_in[2];
    const float* hist_w  = (const float*)d_in[3];
    const float* hist_b  = (const float*)d_in[4];
    const float* wq      = (const float*)d_in[5];
    const float* bq      = (const float*)d_in[6];
    const float* wk      = (const float*)d_in[7];
    const float* bk      = (const float*)d_in[8];
    const float* wv      = (const float*)d_in[9];
    const float* bv      = (const float*)d_in[10];
    const float* wo      = (const float*)d_in[11];
    const float* bo      = (const float*)d_in[12];
    const float* ln1g    = (const float*)d_in[13];
    const float* ln1b    = (const float*)d_in[14];
    const float* fw1     = (const float*)d_in[15];
    const float* fb1     = (const float*)d_in[16];
    const float* fw2     = (const float*)d_in[17];
    const float* fb2     = (const float*)d_in[18];
    const float* ln2g    = (const float*)d_in[19];
    const float* ln2b    = (const float*)d_in[20];
    const float* bng     = (const float*)d_in[21];
    const float* bnb     = (const float*)d_in[22];
    const float* linw    = (const float*)d_in[23];
    const float* linb    = (const float*)d_in[24];
    float* out = (float*)d_out;

    float* pq    = nullptr; cudaGetSymbolAddress((void**)&pq,    d_q);
    float* pk    = nullptr; cudaGetSymbolAddress((void**)&pk,    d_k);
    float* pv    = nullptr; cudaGetSymbolAddress((void**)&pv,    d_v);
    float* poute = nullptr; cudaGetSymbolAddress((void**)&poute, d_oute);
    float* ph1   = nullptr; cudaGetSymbolAddress((void**)&ph1,   d_h1);
    float* ptmp  = nullptr; cudaGetSymbolAddress((void**)&ptmp,  d_tmp);

    Bf16Ptrs bp;
    cudaGetSymbolAddress((void**)&bp.oute_h, d_oute_h);
    cudaGetSymbolAddress((void**)&bp.oute_l, d_oute_l);
    cudaGetSymbolAddress((void**)&bp.qh,  d_qh);
    cudaGetSymbolAddress((void**)&bp.ql,  d_ql);
    cudaGetSymbolAddress((void**)&bp.h1h, d_h1h);
    cudaGetSymbolAddress((void**)&bp.h1l, d_h1l);
    cudaGetSymbolAddress((void**)&bp.ffh, d_ffh);
    cudaGetSymbolAddress((void**)&bp.ffl, d_ffl);
    cudaGetSymbolAddress((void**)&bp.wh,  d_wh);
    cudaGetSymbolAddress((void**)&bp.wl,  d_wl);

    const int TPB = 256;

    // 0. weight split+transpose
    wsplit_sq_kernel<<<(L_ * 4 * 16384 + TPB - 1) / TPB, TPB>>>(wq, wk, wv, wo);
    wsplit_ff_kernel<<<(2 * L_ * 65536 + TPB - 1) / TPB, TPB>>>(fw1, fw2);

    // 1. x + positional encoding (+ out_e split)
    hist_pe_kernel<<<(R_ * D_ + TPB - 1) / TPB, TPB>>>(feat, hist_w, hist_b);

    // 2. transformer layers
    for (int l = 0; l < L_; l++) {
        const __nv_bfloat16* wqh = bp.wh + 0 * 49152 + l * 16384;
        const __nv_bfloat16* wql = bp.wl + 0 * 49152 + l * 16384;
        const __nv_bfloat16* wkh = bp.wh + 1 * 49152 + l * 16384;
        const __nv_bfloat16* wkl = bp.wl + 1 * 49152 + l * 16384;
        const __nv_bfloat16* wvh = bp.wh + 2 * 49152 + l * 16384;
        const __nv_bfloat16* wvl = bp.wl + 2 * 49152 + l * 16384;
        const __nv_bfloat16* woh = bp.wh + 3 * 49152 + l * 16384;
        const __nv_bfloat16* wol = bp.wl + 3 * 49152 + l * 16384;
        const __nv_bfloat16* f1h = bp.wh + 196608 + l * 65536;
        const __nv_bfloat16* f1l = bp.wl + 196608 + l * 65536;
        const __nv_bfloat16* f2h = bp.wh + 393216 + l * 65536;
        const __nv_bfloat16* f2l = bp.wl + 393216 + l * 65536;

        run_gemm(bp.oute_h, bp.oute_l, wqh, wql, bq + l * D_, pq, nullptr, nullptr, R_, D_, D_, 0);
        run_gemm(bp.oute_h, bp.oute_l, wkh, wkl, bk + l * D_, pk, nullptr, nullptr, R_, D_, D_, 0);
        run_gemm(bp.oute_h, bp.oute_l, wvh, wvl, bv + l * D_, pv, nullptr, nullptr, R_, D_, D_, 0);
        attn_kernel<<<B_ * NA_ * H_, 128>>>(pq, pk, pv);
        run_gemm(bp.qh, bp.ql, woh, wol, bo + l * D_, ptmp, nullptr, nullptr, R_, D_, D_, 0);
        add_ln_kernel<<<(R_ * 32 + TPB - 1) / TPB, TPB>>>(poute, ptmp,
            ln1g + l * D_, ln1b + l * D_, ph1, bp.h1h, bp.h1l);
        run_gemm(bp.h1h, bp.h1l, f1h, f1l, fb1 + l * DFF_, nullptr, bp.ffh, bp.ffl,
                 R_, DFF_, D_, 1);
        run_gemm(bp.ffh, bp.ffl, f2h, f2l, fb2 + l * D_, ptmp, nullptr, nullptr,
                 R_, D_, DFF_, 0);
        add_ln_kernel<<<(R_ * 32 + TPB - 1) / TPB, TPB>>>(ph1, ptmp,
            ln2g + l * D_, ln2b + l * D_, poute, bp.oute_h, bp.oute_l);
    }

    // 3. scoring dot products
    sdot_kernel<<<(R_ * 32 + TPB - 1) / TPB, TPB>>>();

    // 4. edge aggregation
    zero_kernel<<<(B_ * NN_ + TPB - 1) / TPB, TPB>>>();
    edge_kernel<<<(B_ * E_ + TPB - 1) / TPB, TPB>>>(eindex, eweight);

    // 5. global batchnorm stats + final outer product
    bnstats_kernel<<<64, TPB>>>();
    final_kernel<<<(R_ * D_ + TPB - 1) / TPB, TPB>>>(bng, bnb, linw, linb, out);
}

// round 6
// speedup vs baseline: 1.3266x; 1.0135x over previous
#include <cuda_runtime.h>
#include <cuda_bf16.h>
#include <cstdint>
#include <math.h>

// Problem constants
#define B_   4
#define NA_  64
#define T_   128
#define D_   128
#define H_   8
#define DH_  16
#define L_   3
#define DFF_ 512
#define E_   65536
#define NN_  (T_ * NA_)        // 8192
#define R_   (B_ * NA_ * T_)   // 32768 rows
#define EPSV 1e-5f

// ---------------- scratch (device globals) ---------------------------------------
__device__ __align__(256) float d_x   [R_ * D_];
__device__ __align__(256) float d_oute[R_ * D_];
__device__ __align__(256) float d_qkv [R_ * 384];
__device__ __align__(256) float d_h1  [R_ * D_];
__device__ __align__(256) float d_s   [B_ * NN_];
__device__ __align__(256) float d_g   [B_ * NN_];
__device__ double d_stats[2];

// bf16 split activations (hi / lo)
__device__ __align__(256) __nv_bfloat16 d_oute_h[R_ * D_];
__device__ __align__(256) __nv_bfloat16 d_oute_l[R_ * D_];
__device__ __align__(256) __nv_bfloat16 d_oh[R_ * D_];     // attention output split
__device__ __align__(256) __nv_bfloat16 d_ol[R_ * D_];
__device__ __align__(256) __nv_bfloat16 d_h1h[R_ * D_];
__device__ __align__(256) __nv_bfloat16 d_h1l[R_ * D_];
__device__ __align__(256) __nv_bfloat16 d_ffh[R_ * DFF_];
__device__ __align__(256) __nv_bfloat16 d_ffl[R_ * DFF_];

// bf16 split transposed weights: [N][K] layout
// QKV: l*49152 + type*16384 + n*128 + k          (type 0..2), total 147456
// O:   147456 + l*16384 + n*128 + k              total -> 196608
// F1:  196608 + l*65536 + n*128 + k   ([512][128])
// F2:  393216 + l*65536 + n*512 + k   ([128][512])
#define W_TOT 589824
__device__ __align__(256) __nv_bfloat16 d_wh[W_TOT];
__device__ __align__(256) __nv_bfloat16 d_wl[W_TOT];
__device__ __align__(256) float d_bqkv[L_ * 384];

// ---------------- helpers --------------------------------------------------------
__device__ __forceinline__ uint32_t smem_u32(const void* p) {
    uint32_t a;
    asm("{ .reg .u64 t; cvta.to.shared.u64 t, %1; cvt.u32.u64 %0, t; }" : "=r"(a) : "l"(p));
    return a;
}
__device__ __forceinline__ void cp16(uint32_t saddr, const void* gptr) {
    asm volatile("cp.async.cg.shared.global [%0], [%1], 16;" :: "r"(saddr), "l"(gptr));
}
#define CP_COMMIT() asm volatile("cp.async.commit_group;" ::: "memory")
#define CP_WAIT(n)  asm volatile("cp.async.wait_group %0;" :: "n"(n) : "memory")

__device__ __forceinline__ void bf16split(float v, __nv_bfloat16& h, __nv_bfloat16& l) {
    h = __float2bfloat16_rn(v);
    l = __float2bfloat16_rn(v - __bfloat162float(h));
}

__device__ __forceinline__ void mma_bf16(float* c, const uint32_t* a,
                                         uint32_t b0, uint32_t b1) {
    asm volatile(
        "mma.sync.aligned.m16n8k16.row.col.f32.bf16.bf16.f32 "
        "{%0,%1,%2,%3}, {%4,%5,%6,%7}, {%8,%9}, {%0,%1,%2,%3};"
        : "+f"(c[0]), "+f"(c[1]), "+f"(c[2]), "+f"(c[3])
        : "r"(a[0]), "r"(a[1]), "r"(a[2]), "r"(a[3]), "r"(b0), "r"(b1));
}

// ---------------- split-bf16 GEMM with cp.async double buffering ------------------
// C = A @ B^T(stored [N][K]) + bias.  Optional fused residual+LayerNorm (N==128).
#define SAB 40
#define ARR_ELEMS (128 * SAB)
#define STAGE_ELEMS (4 * ARR_ELEMS)
#define GEMM_SMEM (2 * STAGE_ELEMS * 2)   // 81920 bytes

__global__ void __launch_bounds__(256, 2)
split_gemm_kernel(const __nv_bfloat16* __restrict__ Ahg, const __nv_bfloat16* __restrict__ Alg,
                  const __nv_bfloat16* __restrict__ Bhg, const __nv_bfloat16* __restrict__ Blg,
                  const float* __restrict__ bias,
                  float* __restrict__ Cf,
                  __nv_bfloat16* __restrict__ Ch, __nv_bfloat16* __restrict__ Cl,
                  int K, int N, int relu,
                  int ln_mode,
                  const float* __restrict__ resid,
                  const float* __restrict__ lng, const float* __restrict__ lnb)
{
    extern __shared__ uint16_t smbuf[];   // [2][4][128*SAB]

    int tid  = threadIdx.x;
    int wid  = tid >> 5;
    int lane = tid & 31;
    int g    = lane >> 2;
    int tg   = lane & 3;
    int warp_m = wid & 3;
    int warp_n = wid >> 2;
    int bm0 = blockIdx.y * 128;
    int bn0 = blockIdx.x * 128;

    const __nv_bfloat16* gbase[4];
    gbase[0] = Ahg + (size_t)bm0 * K;
    gbase[1] = Alg + (size_t)bm0 * K;
    gbase[2] = Bhg + (size_t)bn0 * K;
    gbase[3] = Blg + (size_t)bn0 * K;

    int lrow = tid >> 2;
    int lch  = tid & 3;

    float acc[2][8][4];
#pragma unroll
    for (int mt = 0; mt < 2; mt++)
#pragma unroll
        for (int nt = 0; nt < 8; nt++)
#pragma unroll
            for (int j = 0; j < 4; j++) acc[mt][nt][j] = 0.0f;

    int nch = K >> 5;

    {
        uint16_t* st = smbuf;
#pragma unroll
        for (int arr = 0; arr < 4; arr++) {
            uint16_t* da = st + arr * ARR_ELEMS;
#pragma unroll
            for (int it = 0; it < 2; it++) {
                int row = lrow + it * 64;
                cp16(smem_u32(da + row * SAB + lch * 8),
                     gbase[arr] + (size_t)row * K + lch * 8);
            }
        }
    }
    CP_COMMIT();

    for (int kc = 0; kc < nch; kc++) {
        if (kc + 1 < nch) {
            uint16_t* st = smbuf + ((kc + 1) & 1) * STAGE_ELEMS;
            int koff = (kc + 1) * 32;
#pragma unroll
            for (int arr = 0; arr < 4; arr++) {
                uint16_t* da = st + arr * ARR_ELEMS;
#pragma unroll
                for (int it = 0; it < 2; it++) {
                    int row = lrow + it * 64;
                    cp16(smem_u32(da + row * SAB + lch * 8),
                         gbase[arr] + (size_t)row * K + koff + lch * 8);
                }
            }
            CP_COMMIT();
            CP_WAIT(1);
        } else {
            CP_WAIT(0);
        }
        __syncthreads();

        uint16_t* st = smbuf + (kc & 1) * STAGE_ELEMS;
        uint16_t* Ah = st;
        uint16_t* Al = st + ARR_ELEMS;
        uint16_t* Bh = st + 2 * ARR_ELEMS;
        uint16_t* Bl = st + 3 * ARR_ELEMS;

#pragma unroll
        for (int ks = 0; ks < 2; ks++) {
            int c0 = ks * 16 + 2 * tg;
            uint32_t ah[2][4], al[2][4];
#pragma unroll
            for (int mt = 0; mt < 2; mt++) {
                int r0 = warp_m * 32 + mt * 16 + g;
                ah[mt][0] = *(const uint32_t*)&Ah[r0 * SAB + c0];
                ah[mt][1] = *(const uint32_t*)&Ah[(r0 + 8) * SAB + c0];
                ah[mt][2] = *(const uint32_t*)&Ah[r0 * SAB + c0 + 8];
                ah[mt][3] = *(const uint32_t*)&Ah[(r0 + 8) * SAB + c0 + 8];
                al[mt][0] = *(const uint32_t*)&Al[r0 * SAB + c0];
                al[mt][1] = *(const uint32_t*)&Al[(r0 + 8) * SAB + c0];
                al[mt][2] = *(const uint32_t*)&Al[r0 * SAB + c0 + 8];
                al[mt][3] = *(const uint32_t*)&Al[(r0 + 8) * SAB + c0 + 8];
            }
#pragma unroll
            for (int nt = 0; nt < 8; nt++) {
                int n0 = (warp_n * 64 + nt * 8 + g) * SAB + c0;
                uint32_t bh0 = *(const uint32_t*)&Bh[n0];
                uint32_t bh1 = *(const uint32_t*)&Bh[n0 + 8];
                uint32_t bl0 = *(const uint32_t*)&Bl[n0];
                uint32_t bl1 = *(const uint32_t*)&Bl[n0 + 8];
#pragma unroll
                for (int mt = 0; mt < 2; mt++) {
                    mma_bf16(acc[mt][nt], ah[mt], bh0, bh1);
                    mma_bf16(acc[mt][nt], ah[mt], bl0, bl1);
                    mma_bf16(acc[mt][nt], al[mt], bh0, bh1);
                }
            }
        }
        __syncthreads();
    }

    if (!ln_mode) {
        // ---- standard epilogue: bias (+ReLU), fp32 and/or split stores ----
#pragma unroll
        for (int mt = 0; mt < 2; mt++) {
            int r0 = bm0 + warp_m * 32 + mt * 16 + g;
#pragma unroll
            for (int nt = 0; nt < 8; nt++) {
                int c0 = bn0 + warp_n * 64 + nt * 8 + tg * 2;
                float b0 = bias[c0], b1 = bias[c0 + 1];
                float v0 = acc[mt][nt][0] + b0;
                float v1 = acc[mt][nt][1] + b1;
                float v2 = acc[mt][nt][2] + b0;
                float v3 = acc[mt][nt][3] + b1;
                if (relu) {
                    v0 = fmaxf(v0, 0.0f); v1 = fmaxf(v1, 0.0f);
                    v2 = fmaxf(v2, 0.0f); v3 = fmaxf(v3, 0.0f);
                }
                if (Cf) {
                    *(float2*)(Cf + (size_t)r0 * N + c0)       = make_float2(v0, v1);
                    *(float2*)(Cf + (size_t)(r0 + 8) * N + c0) = make_float2(v2, v3);
                }
                if (Ch) {
                    __nv_bfloat16 h, l;
                    size_t o0 = (size_t)r0 * N + c0;
                    size_t o1 = (size_t)(r0 + 8) * N + c0;
                    bf16split(v0, h, l); Ch[o0]     = h; Cl[o0]     = l;
                    bf16split(v1, h, l); Ch[o0 + 1] = h; Cl[o0 + 1] = l;
                    bf16split(v2, h, l); Ch[o1]     = h; Cl[o1]     = l;
                    bf16split(v3, h, l); Ch[o1 + 1] = h; Cl[o1 + 1] = l;
                }
            }
        }
        return;
    }

    // ---- fused residual + LayerNorm epilogue (N == 128, grid.x == 1) ----
    // h = acc + bias + resid; LN over the 128-col row; outputs fp32 + bf16 split.
    float* pS = (float*)smbuf;            // [128][2]
    float* pQ = pS + 256;                 // [128][2]

    // add bias + residual into acc, accumulate per-row partial sums
#pragma unroll
    for (int mt = 0; mt < 2; mt++) {
#pragma unroll
        for (int half = 0; half < 2; half++) {
            int rl = warp_m * 32 + mt * 16 + g + half * 8;      // CTA-local row
            float s = 0.0f, q = 0.0f;
#pragma unroll
            for (int nt = 0; nt < 8; nt++) {
                int c0 = warp_n * 64 + nt * 8 + tg * 2;
                float2 rv = *(const float2*)(resid + (size_t)(bm0 + rl) * 128 + c0);
                float v0 = acc[mt][nt][2 * half]     + bias[c0]     + rv.x;
                float v1 = acc[mt][nt][2 * half + 1] + bias[c0 + 1] + rv.y;
                acc[mt][nt][2 * half]     = v0;
                acc[mt][nt][2 * half + 1] = v1;
                s += v0 + v1;
                q += v0 * v0 + v1 * v1;
            }
            // reduce over the 4 lanes (tg) holding this row-half
            s += __shfl_xor_sync(0xffffffffu, s, 1);
            q += __shfl_xor_sync(0xffffffffu, q, 1);
            s += __shfl_xor_sync(0xffffffffu, s, 2);
            q += __shfl_xor_sync(0xffffffffu, q, 2);
            if (tg == 0) {
                pS[rl * 2 + warp_n] = s;
                pQ[rl * 2 + warp_n] = q;
            }
        }
    }
    __syncthreads();

#pragma unroll
    for (int mt = 0; mt < 2; mt++) {
#pragma unroll
        for (int half = 0; half < 2; half++) {
            int rl = warp_m * 32 + mt * 16 + g + half * 8;
            float s = pS[rl * 2] + pS[rl * 2 + 1];
            float q = pQ[rl * 2] + pQ[rl * 2 + 1];
            float mu = s * (1.0f / 128.0f);
            float var = q * (1.0f / 128.0f) - mu * mu;
            float inv = rsqrtf(var + EPSV);
            size_t rbase = (size_t)(bm0 + rl) * 128;
#pragma unroll
            for (int nt = 0; nt < 8; nt++) {
                int c0 = warp_n * 64 + nt * 8 + tg * 2;
                float g0 = lng[c0], g1 = lng[c0 + 1];
                float b0 = lnb[c0], b1 = lnb[c0 + 1];
                float v0 = (acc[mt][nt][2 * half]     - mu) * inv * g0 + b0;
                float v1 = (acc[mt][nt][2 * half + 1] - mu) * inv * g1 + b1;
                *(float2*)(Cf + rbase + c0) = make_float2(v0, v1);
                __nv_bfloat16 hh, ll;
                bf16split(v0, hh, ll); Ch[rbase + c0]     = hh; Cl[rbase + c0]     = ll;
                bf16split(v1, hh, ll); Ch[rbase + c0 + 1] = hh; Cl[rbase + c0 + 1] = ll;
            }
        }
    }
}

// ---------------- weight split+transpose kernels ---------------------------------
__global__ void wsplit_sq_kernel(const float* __restrict__ wq, const float* __restrict__ wk,
                                 const float* __restrict__ wv, const float* __restrict__ wo,
                                 const float* __restrict__ bq, const float* __restrict__ bk,
                                 const float* __restrict__ bv)
{
    int idx = blockIdx.x * blockDim.x + threadIdx.x;
    if (idx < L_ * 384) {   // combined QKV bias
        int l = idx / 384, j = idx % 384;
        float v = (j < 128) ? bq[l * 128 + j] :
                  (j < 256) ? bk[l * 128 + j - 128] : bv[l * 128 + j - 256];
        d_bqkv[idx] = v;
    }
    if (idx >= L_ * 4 * 16384) return;
    int type = idx / (L_ * 16384);
    int rem  = idx % (L_ * 16384);
    int l    = rem / 16384;
    int kn   = rem % 16384;
    int k = kn >> 7, n = kn & 127;
    const float* src = (type == 0) ? wq : (type == 1) ? wk : (type == 2) ? wv : wo;
    float v = src[l * 16384 + k * 128 + n];
    __nv_bfloat16 h, lo;
    bf16split(v, h, lo);
    int off = (type < 3) ? (l * 49152 + type * 16384 + n * 128 + k)
                         : (147456 + l * 16384 + n * 128 + k);
    d_wh[off] = h; d_wl[off] = lo;
}

__global__ void wsplit_ff_kernel(const float* __restrict__ f1, const float* __restrict__ f2)
{
    int idx = blockIdx.x * blockDim.x + threadIdx.x;
    if (idx >= 2 * L_ * 65536) return;
    float v; int off;
    if (idx < L_ * 65536) {                  // f1: [l][k<128][n<512] -> [l][n][k]
        int l = idx / 65536, kn = idx % 65536;
        int k = kn >> 9, n = kn & 511;
        v = f1[l * 65536 + k * 512 + n];
        off = 196608 + l * 65536 + n * 128 + k;
    } else {                                 // f2: [l][k<512][n<128] -> [l][n][k]
        int j = idx - L_ * 65536;
        int l = j / 65536, kn = j % 65536;
        int k = kn >> 7, n = kn & 127;
        v = f2[l * 65536 + k * 128 + n];
        off = 393216 + l * 65536 + n * 512 + k;
    }
    __nv_bfloat16 h, lo;
    bf16split(v, h, lo);
    d_wh[off] = h; d_wl[off] = lo;
}

// ---------------- kernel 1: hist projection + positional encoding ----------------
__global__ void hist_pe_kernel(const float* __restrict__ feat,
                               const float* __restrict__ hw,
                               const float* __restrict__ hb)
{
    int idx = blockIdx.x * blockDim.x + threadIdx.x;
    if (idx >= R_ * D_) return;
    int row = idx >> 7;
    int d   = idx & 127;
    int t   = row & (T_ - 1);
    const float* f = feat + (size_t)row * 3;
    float xv = fmaf(f[0], hw[d],
               fmaf(f[1], hw[D_ + d],
               fmaf(f[2], hw[2 * D_ + d], hb[d])));
    d_x[idx] = xv;
    int j2 = d & ~1;
    float ang = (float)t * __expf(-9.210340371976184f * (float)j2 / 128.0f);
    float pe = (d & 1) ? cosf(ang) : sinf(ang);
    float oe = xv + pe;
    d_oute[idx] = oe;
    __nv_bfloat16 h, l;
    bf16split(oe, h, l);
    d_oute_h[idx] = h; d_oute_l[idx] = l;
}

// ---------------- attention per (b,n,h); reads fused qkv, writes split O --------
__global__ __launch_bounds__(128)
void attn_kernel()
{
    int blk = blockIdx.x;
    int h   = blk % H_;
    int bn  = blk / H_;
    const float* base = d_qkv + (size_t)bn * T_ * 384;

    __shared__ float Ks[T_][DH_];
    __shared__ float Vs[T_][DH_];
    int tid = threadIdx.x;
    for (int i = tid; i < T_ * DH_; i += 128) {
        int r = i >> 4, c = i & 15;
        Ks[r][c] = base[(size_t)r * 384 + 128 + h * DH_ + c];
        Vs[r][c] = base[(size_t)r * 384 + 256 + h * DH_ + c];
    }
    __syncthreads();

    const float* qrow = base + (size_t)tid * 384 + h * DH_;
    const float scale = 0.25f;
    float qr[DH_];
#pragma unroll
    for (int d = 0; d < DH_; d++) qr[d] = qrow[d] * scale;

    float m = -INFINITY, l = 0.0f;
    float acc[DH_];
#pragma unroll
    for (int d = 0; d < DH_; d++) acc[d] = 0.0f;

    for (int kk = 0; kk < T_; kk++) {
        float sc = 0.0f;
#pragma unroll
        for (int d = 0; d < DH_; d++) sc = fmaf(qr[d], Ks[kk][d], sc);
        float mn = fmaxf(m, sc);
        float corr = __expf(m - mn);
        float p = __expf(sc - mn);
        l = l * corr + p;
#pragma unroll
        for (int d = 0; d < DH_; d++) acc[d] = fmaf(acc[d], corr, p * Vs[kk][d]);
        m = mn;
    }
    float inv = 1.0f / l;
    size_t rowoff = (size_t)bn * T_ * D_ + (size_t)tid * D_ + h * DH_;
#pragma unroll
    for (int d = 0; d < DH_; d++) {
        float o = acc[d] * inv;
        __nv_bfloat16 hh, ll;
        bf16split(o, hh, ll);
        d_oh[rowoff + d] = hh;
        d_ol[rowoff + d] = ll;
    }
}

// ---------------- s[b, t*NA+n] = dot(out_e, x) ----------------------------------
__global__ void sdot_kernel()
{
    int warp = (blockIdx.x * blockDim.x + threadIdx.x) >> 5;
    int lane = threadIdx.x & 31;
    if (warp >= R_) return;
    size_t base = (size_t)warp * D_ + lane * 4;
    float4 w4 = *(const float4*)(d_oute + base);
    float4 x4 = *(const float4*)(d_x + base);
    float dt = w4.x * x4.x + w4.y * x4.y + w4.z * x4.z + w4.w * x4.w;
#pragma unroll
    for (int o = 16; o; o >>= 1) dt += __shfl_xor_sync(0xffffffffu, dt, o);
    if (lane == 0) {
        int b = warp / (NA_ * T_);
        int rem = warp % (NA_ * T_);
        int n = rem / T_;
        int t = rem % T_;
        d_s[b * NN_ + t * NA_ + n] = dt;
    }
}

// ---------------- zero accumulators ---------------------------------------------
__global__ void zero_kernel()
{
    int i = blockIdx.x * blockDim.x + threadIdx.x;
    if (i < B_ * NN_) d_g[i] = 0.0f;
    if (i < 2) d_stats[i] = 0.0;
}

// ---------------- edge aggregation ----------------------------------------------
__global__ void edge_kernel(const int* __restrict__ ei, const float* __restrict__ ew)
{
    int gid = blockIdx.x * blockDim.x + threadIdx.x;
    if (gid >= B_ * E_) return;
    int b = gid / E_;
    int e = gid % E_;
    const int* eb = ei + (size_t)b * 2 * E_;
    int src = eb[e];
    int dst = eb[E_ + e];
    atomicAdd(&d_g[b * NN_ + dst], ew[(size_t)b * E_ + e] * d_s[b * NN_ + src]);
}

// ---------------- global batchnorm stats (double precision) ---------------------
__global__ void bnstats_kernel()
{
    double s = 0.0, sq = 0.0;
    for (int i = blockIdx.x * blockDim.x + threadIdx.x; i < B_ * NN_;
         i += gridDim.x * blockDim.x) {
        double v = (double)d_g[i];
        s += v; sq += v * v;
    }
#pragma unroll
    for (int o = 16; o; o >>= 1) {
        s  += __shfl_xor_sync(0xffffffffu, s, o);
        sq += __shfl_xor_sync(0xffffffffu, sq, o);
    }
    if ((threadIdx.x & 31) == 0) {
        atomicAdd(&d_stats[0], s);
        atomicAdd(&d_stats[1], sq);
    }
}

// ---------------- final outer product -------------------------------------------
__global__ void final_kernel(const float* __restrict__ bng, const float* __restrict__ bnb,
                             const float* __restrict__ lw, const float* __restrict__ lb,
                             float* __restrict__ out)
{
    int idx = blockIdx.x * blockDim.x + threadIdx.x;
    if (idx >= R_ * D_) return;
    int d   = idx & 127;
    int row = idx >> 7;
    int t   = row & 127;
    int bn  = row >> 7;
    int b   = bn >> 6;
    int n   = bn & 63;
    double mu  = d_stats[0] * (1.0 / 32768.0);
    double var = d_stats[1] * (1.0 / 32768.0) - mu * mu;
    float inv = rsqrtf((float)var + EPSV);
    float gval = d_g[b * NN_ + t * NA_ + n];
    float ghat = ((gval - (float)mu) * inv) * bng[0] + bnb[0];
    out[idx] = ghat * lw[d] + lb[d];
}

// ---------------- launcher -------------------------------------------------------
extern "C" void kernel_launch(void* const* d_in, const int* in_sizes, int n_in,
                              void* d_out, int out_size)
{
    const float* feat    = (const float*)d_in[0];
    const int*   eindex  = (const int*)  d_in[1];
    const float* eweight = (const float*)d_in[2];
    const float* hist_w  = (const float*)d_in[3];
    const float* hist_b  = (const float*)d_in[4];
    const float* wq      = (const float*)d_in[5];
    const float* bq      = (const float*)d_in[6];
    const float* wk      = (const float*)d_in[7];
    const float* bk      = (const float*)d_in[8];
    const float* wv      = (const float*)d_in[9];
    const float* bv      = (const float*)d_in[10];
    const float* wo      = (const float*)d_in[11];
    const float* bo      = (const float*)d_in[12];
    const float* ln1g    = (const float*)d_in[13];
    const float* ln1b    = (const float*)d_in[14];
    const float* fw1     = (const float*)d_in[15];
    const float* fb1     = (const float*)d_in[16];
    const float* fw2     = (const float*)d_in[17];
    const float* fb2     = (const float*)d_in[18];
    const float* ln2g    = (const float*)d_in[19];
    const float* ln2b    = (const float*)d_in[20];
    const float* bng     = (const float*)d_in[21];
    const float* bnb     = (const float*)d_in[22];
    const float* linw    = (const float*)d_in[23];
    const float* linb    = (const float*)d_in[24];
    float* out = (float*)d_out;

    float* pqkv = nullptr; cudaGetSymbolAddress((void**)&pqkv, d_qkv);
    float* poute = nullptr; cudaGetSymbolAddress((void**)&poute, d_oute);
    float* ph1  = nullptr; cudaGetSymbolAddress((void**)&ph1, d_h1);
    float* pbqkv = nullptr; cudaGetSymbolAddress((void**)&pbqkv, d_bqkv);

    __nv_bfloat16 *poute_h, *poute_l, *poh, *pol, *ph1h, *ph1l, *pffh, *pffl, *pwh, *pwl;
    cudaGetSymbolAddress((void**)&poute_h, d_oute_h);
    cudaGetSymbolAddress((void**)&poute_l, d_oute_l);
    cudaGetSymbolAddress((void**)&poh,  d_oh);
    cudaGetSymbolAddress((void**)&pol,  d_ol);
    cudaGetSymbolAddress((void**)&ph1h, d_h1h);
    cudaGetSymbolAddress((void**)&ph1l, d_h1l);
    cudaGetSymbolAddress((void**)&pffh, d_ffh);
    cudaGetSymbolAddress((void**)&pffl, d_ffl);
    cudaGetSymbolAddress((void**)&pwh,  d_wh);
    cudaGetSymbolAddress((void**)&pwl,  d_wl);

    cudaFuncSetAttribute(split_gemm_kernel,
                         cudaFuncAttributeMaxDynamicSharedMemorySize, GEMM_SMEM);

    const int TPB = 256;

    // 0. weight split+transpose (+ fused QKV bias)
    wsplit_sq_kernel<<<(L_ * 4 * 16384 + TPB - 1) / TPB, TPB>>>(wq, wk, wv, wo, bq, bk, bv);
    wsplit_ff_kernel<<<(2 * L_ * 65536 + TPB - 1) / TPB, TPB>>>(fw1, fw2);

    // 1. x + positional encoding (+ out_e split)
    hist_pe_kernel<<<(R_ * D_ + TPB - 1) / TPB, TPB>>>(feat, hist_w, hist_b);

    // 2. transformer layers (5 launches each)
    for (int l = 0; l < L_; l++) {
        const __nv_bfloat16* wqkvh = pwh + l * 49152;
        const __nv_bfloat16* wqkvl = pwl + l * 49152;
        const __nv_bfloat16* woh = pwh + 147456 + l * 16384;
        const __nv_bfloat16* wol = pwl + 147456 + l * 16384;
        const __nv_bfloat16* f1h = pwh + 196608 + l * 65536;
        const __nv_bfloat16* f1l = pwl + 196608 + l * 65536;
        const __nv_bfloat16* f2h = pwh + 393216 + l * 65536;
        const __nv_bfloat16* f2l = pwl + 393216 + l * 65536;

        // fused QKV: N=384
        split_gemm_kernel<<<dim3(3, R_ / 128), 256, GEMM_SMEM>>>(
            poute_h, poute_l, wqkvh, wqkvl, pbqkv + l * 384,
            pqkv, nullptr, nullptr, D_, 384, 0, 0, nullptr, nullptr, nullptr);

        attn_kernel<<<B_ * NA_ * H_, 128>>>();

        // O-proj + residual + LN1 -> h1 (fp32 + split)
        split_gemm_kernel<<<dim3(1, R_ / 128), 256, GEMM_SMEM>>>(
            poh, pol, woh, wol, bo + l * D_,
            ph1, ph1h, ph1l, D_, D_, 0, 1, poute, ln1g + l * D_, ln1b + l * D_);

        // FFN-1 (ReLU), split-only output
        split_gemm_kernel<<<dim3(4, R_ / 128), 256, GEMM_SMEM>>>(
            ph1h, ph1l, f1h, f1l, fb1 + l * DFF_,
            nullptr, pffh, pffl, D_, DFF_, 1, 0, nullptr, nullptr, nullptr);

        // FFN-2 + residual + LN2 -> oute (fp32 + split)
        split_gemm_kernel<<<dim3(1, R_ / 128), 256, GEMM_SMEM>>>(
            pffh, pffl, f2h, f2l, fb2 + l * D_,
            poute, poute_h, poute_l, DFF_, D_, 0, 1, ph1, ln2g + l * D_, ln2b + l * D_);
    }

    // 3. scoring dot products
    sdot_kernel<<<(R_ * 32 + TPB - 1) / TPB, TPB>>>();

    // 4. edge aggregation
    zero_kernel<<<(B_ * NN_ + TPB - 1) / TPB, TPB>>>();
    edge_kernel<<<(B_ * E_ + TPB - 1) / TPB, TPB>>>(eindex, eweight);

    // 5. global batchnorm stats + final outer product
    bnstats_kernel<<<64, TPB>>>();
    final_kernel<<<(R_ * D_ + TPB - 1) / TPB, TPB>>>(bng, bnb, linw, linb, out);
}

// round 7
// speedup vs baseline: 1.5708x; 1.1841x over previous
#include <cuda_runtime.h>
#include <cuda_bf16.h>
#include <cstdint>
#include <math.h>

// Problem constants
#define B_   4
#define NA_  64
#define T_   128
#define D_   128
#define H_   8
#define DH_  16
#define L_   3
#define DFF_ 512
#define E_   65536
#define NN_  (T_ * NA_)        // 8192
#define R_   (B_ * NA_ * T_)   // 32768 rows
#define EPSV 1e-5f

// ---------------- scratch (device globals) ---------------------------------------
__device__ __align__(256) float d_x   [R_ * D_];
__device__ __align__(256) float d_oute[R_ * D_];
__device__ __align__(256) float d_qkv [R_ * 384];
__device__ __align__(256) float d_h1  [R_ * D_];
__device__ __align__(256) float d_s   [B_ * NN_];
__device__ __align__(256) float d_g   [B_ * NN_];
__device__ double d_stats[2];

// bf16 split activations (hi / lo)
__device__ __align__(256) __nv_bfloat16 d_oute_h[R_ * D_];
__device__ __align__(256) __nv_bfloat16 d_oute_l[R_ * D_];
__device__ __align__(256) __nv_bfloat16 d_oh[R_ * D_];
__device__ __align__(256) __nv_bfloat16 d_ol[R_ * D_];
__device__ __align__(256) __nv_bfloat16 d_h1h[R_ * D_];
__device__ __align__(256) __nv_bfloat16 d_h1l[R_ * D_];
__device__ __align__(256) __nv_bfloat16 d_ffh[R_ * DFF_];
__device__ __align__(256) __nv_bfloat16 d_ffl[R_ * DFF_];

// bf16 split transposed weights ([N][K]):
// QKV: l*49152 + type*16384 ; O: 147456 + l*16384 ; F1: 196608 + l*65536 ; F2: 393216 + l*65536
#define W_TOT 589824
__device__ __align__(256) __nv_bfloat16 d_wh[W_TOT];
__device__ __align__(256) __nv_bfloat16 d_wl[W_TOT];
__device__ __align__(256) float d_bqkv[L_ * 384];

// ---------------- helpers --------------------------------------------------------
__device__ __forceinline__ uint32_t smem_u32(const void* p) {
    uint32_t a;
    asm("{ .reg .u64 t; cvta.to.shared.u64 t, %1; cvt.u32.u64 %0, t; }" : "=r"(a) : "l"(p));
    return a;
}
__device__ __forceinline__ void cp16(uint32_t saddr, const void* gptr) {
    asm volatile("cp.async.cg.shared.global [%0], [%1], 16;" :: "r"(saddr), "l"(gptr));
}
#define CP_COMMIT() asm volatile("cp.async.commit_group;" ::: "memory")
#define CP_WAIT(n)  asm volatile("cp.async.wait_group %0;" :: "n"(n) : "memory")

__device__ __forceinline__ void bf16split(float v, __nv_bfloat16& h, __nv_bfloat16& l) {
    h = __float2bfloat16_rn(v);
    l = __float2bfloat16_rn(v - __bfloat162float(h));
}
__device__ __forceinline__ uint32_t packsplit_h(float v0, float v1) {
    __nv_bfloat16 h0 = __float2bfloat16_rn(v0);
    __nv_bfloat16 h1 = __float2bfloat16_rn(v1);
    return (uint32_t)__bfloat16_as_ushort(h0) | ((uint32_t)__bfloat16_as_ushort(h1) << 16);
}
__device__ __forceinline__ uint32_t packsplit_l(float v0, float v1) {
    __nv_bfloat16 h0 = __float2bfloat16_rn(v0);
    __nv_bfloat16 h1 = __float2bfloat16_rn(v1);
    __nv_bfloat16 l0 = __float2bfloat16_rn(v0 - __bfloat162float(h0));
    __nv_bfloat16 l1 = __float2bfloat16_rn(v1 - __bfloat162float(h1));
    return (uint32_t)__bfloat16_as_ushort(l0) | ((uint32_t)__bfloat16_as_ushort(l1) << 16);
}

__device__ __forceinline__ void mma_bf16(float* c, const uint32_t* a,
                                         uint32_t b0, uint32_t b1) {
    asm volatile(
        "mma.sync.aligned.m16n8k16.row.col.f32.bf16.bf16.f32 "
        "{%0,%1,%2,%3}, {%4,%5,%6,%7}, {%8,%9}, {%0,%1,%2,%3};"
        : "+f"(c[0]), "+f"(c[1]), "+f"(c[2]), "+f"(c[3])
        : "r"(a[0]), "r"(a[1]), "r"(a[2]), "r"(a[3]), "r"(b0), "r"(b1));
}

// ================= persistent-B GEMM (K=128): C = A @ B^T + bias ================
// B (128n x 128k, hi+lo) resident in smem; MT M-tiles streamed per CTA.
#define SAB 40
#define SBB 136
#define PG_B_ELEMS (128 * SBB)            // 17408 per array
#define PG_A_ELEMS (128 * SAB)            // 5120 per array
#define PG_A_OFF   (2 * PG_B_ELEMS)       // 34816
#define PG_LN_OFF  (PG_A_OFF + 4 * PG_A_ELEMS)  // 55296 elems
#define PG_SMEM    ((PG_LN_OFF) * 2 + 2048)     // 112640 bytes

__global__ void __launch_bounds__(256, 2)
pgemm_kernel(const __nv_bfloat16* __restrict__ Ahg, const __nv_bfloat16* __restrict__ Alg,
             const __nv_bfloat16* __restrict__ Bhg, const __nv_bfloat16* __restrict__ Blg,
             const float* __restrict__ bias,
             float* __restrict__ Cf,
             __nv_bfloat16* __restrict__ Ch, __nv_bfloat16* __restrict__ Cl,
             int N, int relu, int ln_mode,
             const float* __restrict__ resid,
             const float* __restrict__ lng, const float* __restrict__ lnb,
             int MT)
{
    extern __shared__ uint16_t sm[];
    uint16_t* Bh = sm;
    uint16_t* Bl = sm + PG_B_ELEMS;
    uint16_t* Ast = sm + PG_A_OFF;           // [2 stages][2 arrays][5120]
    float* pS = (float*)(sm + PG_LN_OFF);    // [128][2]
    float* pQ = pS + 256;

    int tid  = threadIdx.x;
    int wid  = tid >> 5;
    int lane = tid & 31;
    int g    = lane >> 2;
    int tg   = lane & 3;
    int warp_m = wid & 3;
    int warp_n = wid >> 2;
    int bn0 = blockIdx.x * 128;
    int bm0 = blockIdx.y * (MT << 7);

    // ---- load full B tile (hi+lo) via cp.async ----
    {
        const uint16_t* bh = (const uint16_t*)Bhg + (size_t)bn0 * 128;
        const uint16_t* bl = (const uint16_t*)Blg + (size_t)bn0 * 128;
#pragma unroll
        for (int it = 0; it < 8; it++) {
            int idx = it * 256 + tid;
            int row = idx >> 4, ch = idx & 15;
            cp16(smem_u32(Bh + row * SBB + ch * 8), bh + row * 128 + ch * 8);
            cp16(smem_u32(Bl + row * SBB + ch * 8), bl + row * 128 + ch * 8);
        }
    }

    int lrow = tid >> 2;       // 0..63
    int lch  = tid & 3;

    const uint16_t* ahg = (const uint16_t*)Ahg;
    const uint16_t* alg = (const uint16_t*)Alg;

    int NC = MT << 2;          // 4 chunks per M-tile (K=128, BK=32)

    // prologue: A chunk 0 into stage 0 (committed together with B)
    {
        uint16_t* dh = Ast;
        uint16_t* dl = Ast + PG_A_ELEMS;
        const uint16_t* ah = ahg + (size_t)bm0 * 128;
        const uint16_t* al = alg + (size_t)bm0 * 128;
#pragma unroll
        for (int it = 0; it < 2; it++) {
            int row = lrow + it * 64;
            cp16(smem_u32(dh + row * SAB + lch * 8), ah + (size_t)row * 128 + lch * 8);
            cp16(smem_u32(dl + row * SAB + lch * 8), al + (size_t)row * 128 + lch * 8);
        }
    }
    CP_COMMIT();

    float acc[2][8][4];
#pragma unroll
    for (int mt = 0; mt < 2; mt++)
#pragma unroll
        for (int nt = 0; nt < 8; nt++)
#pragma unroll
            for (int j = 0; j < 4; j++) acc[mt][nt][j] = 0.0f;

    for (int c = 0; c < NC; c++) {
        if (c + 1 < NC) {
            int nmt = (c + 1) >> 2, nkc = (c + 1) & 3;
            uint16_t* dh = Ast + ((c + 1) & 1) * (2 * PG_A_ELEMS);
            uint16_t* dl = dh + PG_A_ELEMS;
            const uint16_t* ah = ahg + (size_t)(bm0 + (nmt << 7)) * 128 + nkc * 32;
            const uint16_t* al = alg + (size_t)(bm0 + (nmt << 7)) * 128 + nkc * 32;
#pragma unroll
            for (int it = 0; it < 2; it++) {
                int row = lrow + it * 64;
                cp16(smem_u32(dh + row * SAB + lch * 8), ah + (size_t)row * 128 + lch * 8);
                cp16(smem_u32(dl + row * SAB + lch * 8), al + (size_t)row * 128 + lch * 8);
            }
            CP_COMMIT();
            CP_WAIT(1);
        } else {
            CP_WAIT(0);
        }
        __syncthreads();

        uint16_t* Ah = Ast + (c & 1) * (2 * PG_A_ELEMS);
        uint16_t* Al = Ah + PG_A_ELEMS;
        int kc = c & 3;

#pragma unroll
        for (int ks = 0; ks < 2; ks++) {
            int ac0 = ks * 16 + 2 * tg;            // col within A chunk
            int bc0 = kc * 32 + ks * 16 + 2 * tg;  // col within resident B (full K)
            uint32_t ah[2][4], al[2][4];
#pragma unroll
            for (int mt = 0; mt < 2; mt++) {
                int r0 = warp_m * 32 + mt * 16 + g;
                ah[mt][0] = *(const uint32_t*)&Ah[r0 * SAB + ac0];
                ah[mt][1] = *(const uint32_t*)&Ah[(r0 + 8) * SAB + ac0];
                ah[mt][2] = *(const uint32_t*)&Ah[r0 * SAB + ac0 + 8];
                ah[mt][3] = *(const uint32_t*)&Ah[(r0 + 8) * SAB + ac0 + 8];
                al[mt][0] = *(const uint32_t*)&Al[r0 * SAB + ac0];
                al[mt][1] = *(const uint32_t*)&Al[(r0 + 8) * SAB + ac0];
                al[mt][2] = *(const uint32_t*)&Al[r0 * SAB + ac0 + 8];
                al[mt][3] = *(const uint32_t*)&Al[(r0 + 8) * SAB + ac0 + 8];
            }
#pragma unroll
            for (int nt = 0; nt < 8; nt++) {
                int n0 = (warp_n * 64 + nt * 8 + g) * SBB + bc0;
                uint32_t bh0 = *(const uint32_t*)&Bh[n0];
                uint32_t bh1 = *(const uint32_t*)&Bh[n0 + 8];
                uint32_t bl0 = *(const uint32_t*)&Bl[n0];
                uint32_t bl1 = *(const uint32_t*)&Bl[n0 + 8];
#pragma unroll
                for (int mt = 0; mt < 2; mt++) {
                    mma_bf16(acc[mt][nt], ah[mt], bh0, bh1);
                    mma_bf16(acc[mt][nt], ah[mt], bl0, bl1);
                    mma_bf16(acc[mt][nt], al[mt], bh0, bh1);
                }
            }
        }

        if (kc == 3) {
            // ---- end of M-tile: epilogue ----
            int mt_i = c >> 2;
            int rbm = bm0 + (mt_i << 7);
            if (!ln_mode) {
#pragma unroll
                for (int mt = 0; mt < 2; mt++) {
                    int r0 = rbm + warp_m * 32 + mt * 16 + g;
#pragma unroll
                    for (int nt = 0; nt < 8; nt++) {
                        int c0 = bn0 + warp_n * 64 + nt * 8 + tg * 2;
                        float b0 = bias[c0], b1 = bias[c0 + 1];
                        float v0 = acc[mt][nt][0] + b0;
                        float v1 = acc[mt][nt][1] + b1;
                        float v2 = acc[mt][nt][2] + b0;
                        float v3 = acc[mt][nt][3] + b1;
                        if (relu) {
                            v0 = fmaxf(v0, 0.0f); v1 = fmaxf(v1, 0.0f);
                            v2 = fmaxf(v2, 0.0f); v3 = fmaxf(v3, 0.0f);
                        }
                        if (Cf) {
                            *(float2*)(Cf + (size_t)r0 * N + c0)       = make_float2(v0, v1);
                            *(float2*)(Cf + (size_t)(r0 + 8) * N + c0) = make_float2(v2, v3);
                        }
                        if (Ch) {
                            size_t o0 = (size_t)r0 * N + c0;
                            size_t o1 = (size_t)(r0 + 8) * N + c0;
                            *(uint32_t*)(Ch + o0) = packsplit_h(v0, v1);
                            *(uint32_t*)(Cl + o0) = packsplit_l(v0, v1);
                            *(uint32_t*)(Ch + o1) = packsplit_h(v2, v3);
                            *(uint32_t*)(Cl + o1) = packsplit_l(v2, v3);
                        }
                    }
                }
            } else {
                // fused residual + LayerNorm (N == 128, grid.x == 1)
#pragma unroll
                for (int mt = 0; mt < 2; mt++) {
#pragma unroll
                    for (int half = 0; half < 2; half++) {
                        int rl = warp_m * 32 + mt * 16 + g + half * 8;
                        float s = 0.0f, q = 0.0f;
#pragma unroll
                        for (int nt = 0; nt < 8; nt++) {
                            int c0 = warp_n * 64 + nt * 8 + tg * 2;
                            float2 rv = *(const float2*)(resid + (size_t)(rbm + rl) * 128 + c0);
                            float v0 = acc[mt][nt][2 * half]     + bias[c0]     + rv.x;
                            float v1 = acc[mt][nt][2 * half + 1] + bias[c0 + 1] + rv.y;
                            acc[mt][nt][2 * half]     = v0;
                            acc[mt][nt][2 * half + 1] = v1;
                            s += v0 + v1;
                            q += v0 * v0 + v1 * v1;
                        }
                        s += __shfl_xor_sync(0xffffffffu, s, 1);
                        q += __shfl_xor_sync(0xffffffffu, q, 1);
                        s += __shfl_xor_sync(0xffffffffu, s, 2);
                        q += __shfl_xor_sync(0xffffffffu, q, 2);
                        if (tg == 0) {
                            pS[rl * 2 + warp_n] = s;
                            pQ[rl * 2 + warp_n] = q;
                        }
                    }
                }
                __syncthreads();
#pragma unroll
                for (int mt = 0; mt < 2; mt++) {
#pragma unroll
                    for (int half = 0; half < 2; half++) {
                        int rl = warp_m * 32 + mt * 16 + g + half * 8;
                        float s = pS[rl * 2] + pS[rl * 2 + 1];
                        float q = pQ[rl * 2] + pQ[rl * 2 + 1];
                        float mu = s * (1.0f / 128.0f);
                        float var = q * (1.0f / 128.0f) - mu * mu;
                        float inv = rsqrtf(var + EPSV);
                        size_t rbase = (size_t)(rbm + rl) * 128;
#pragma unroll
                        for (int nt = 0; nt < 8; nt++) {
                            int c0 = warp_n * 64 + nt * 8 + tg * 2;
                            float v0 = (acc[mt][nt][2 * half]     - mu) * inv * lng[c0]     + lnb[c0];
                            float v1 = (acc[mt][nt][2 * half + 1] - mu) * inv * lng[c0 + 1] + lnb[c0 + 1];
                            *(float2*)(Cf + rbase + c0) = make_float2(v0, v1);
                            *(uint32_t*)(Ch + rbase + c0) = packsplit_h(v0, v1);
                            *(uint32_t*)(Cl + rbase + c0) = packsplit_l(v0, v1);
                        }
                    }
                }
            }
            // reset accumulators for next M-tile
#pragma unroll
            for (int mt = 0; mt < 2; mt++)
#pragma unroll
                for (int nt = 0; nt < 8; nt++)
#pragma unroll
                    for (int j = 0; j < 4; j++) acc[mt][nt][j] = 0.0f;
        }
        __syncthreads();
    }
}

// ---------------- chunked split-bf16 GEMM (for K=512 FF2) ------------------------
#define ARR_ELEMS (128 * SAB)
#define STAGE_ELEMS (4 * ARR_ELEMS)
#define GEMM_SMEM (2 * STAGE_ELEMS * 2)

__global__ void __launch_bounds__(256, 2)
split_gemm_kernel(const __nv_bfloat16* __restrict__ Ahg, const __nv_bfloat16* __restrict__ Alg,
                  const __nv_bfloat16* __restrict__ Bhg, const __nv_bfloat16* __restrict__ Blg,
                  const float* __restrict__ bias,
                  float* __restrict__ Cf,
                  __nv_bfloat16* __restrict__ Ch, __nv_bfloat16* __restrict__ Cl,
                  int K, int N, int relu,
                  int ln_mode,
                  const float* __restrict__ resid,
                  const float* __restrict__ lng, const float* __restrict__ lnb)
{
    extern __shared__ uint16_t smbuf[];

    int tid  = threadIdx.x;
    int wid  = tid >> 5;
    int lane = tid & 31;
    int g    = lane >> 2;
    int tg   = lane & 3;
    int warp_m = wid & 3;
    int warp_n = wid >> 2;
    int bm0 = blockIdx.y * 128;
    int bn0 = blockIdx.x * 128;

    const __nv_bfloat16* gbase[4];
    gbase[0] = Ahg + (size_t)bm0 * K;
    gbase[1] = Alg + (size_t)bm0 * K;
    gbase[2] = Bhg + (size_t)bn0 * K;
    gbase[3] = Blg + (size_t)bn0 * K;

    int lrow = tid >> 2;
    int lch  = tid & 3;

    float acc[2][8][4];
#pragma unroll
    for (int mt = 0; mt < 2; mt++)
#pragma unroll
        for (int nt = 0; nt < 8; nt++)
#pragma unroll
            for (int j = 0; j < 4; j++) acc[mt][nt][j] = 0.0f;

    int nch = K >> 5;

    {
        uint16_t* st = smbuf;
#pragma unroll
        for (int arr = 0; arr < 4; arr++) {
            uint16_t* da = st + arr * ARR_ELEMS;
#pragma unroll
            for (int it = 0; it < 2; it++) {
                int row = lrow + it * 64;
                cp16(smem_u32(da + row * SAB + lch * 8),
                     gbase[arr] + (size_t)row * K + lch * 8);
            }
        }
    }
    CP_COMMIT();

    for (int kc = 0; kc < nch; kc++) {
        if (kc + 1 < nch) {
            uint16_t* st = smbuf + ((kc + 1) & 1) * STAGE_ELEMS;
            int koff = (kc + 1) * 32;
#pragma unroll
            for (int arr = 0; arr < 4; arr++) {
                uint16_t* da = st + arr * ARR_ELEMS;
#pragma unroll
                for (int it = 0; it < 2; it++) {
                    int row = lrow + it * 64;
                    cp16(smem_u32(da + row * SAB + lch * 8),
                         gbase[arr] + (size_t)row * K + koff + lch * 8);
                }
            }
            CP_COMMIT();
            CP_WAIT(1);
        } else {
            CP_WAIT(0);
        }
        __syncthreads();

        uint16_t* st = smbuf + (kc & 1) * STAGE_ELEMS;
        uint16_t* Ah = st;
        uint16_t* Al = st + ARR_ELEMS;
        uint16_t* Bh = st + 2 * ARR_ELEMS;
        uint16_t* Bl = st + 3 * ARR_ELEMS;

#pragma unroll
        for (int ks = 0; ks < 2; ks++) {
            int c0 = ks * 16 + 2 * tg;
            uint32_t ah[2][4], al[2][4];
#pragma unroll
            for (int mt = 0; mt < 2; mt++) {
                int r0 = warp_m * 32 + mt * 16 + g;
                ah[mt][0] = *(const uint32_t*)&Ah[r0 * SAB + c0];
                ah[mt][1] = *(const uint32_t*)&Ah[(r0 + 8) * SAB + c0];
                ah[mt][2] = *(const uint32_t*)&Ah[r0 * SAB + c0 + 8];
                ah[mt][3] = *(const uint32_t*)&Ah[(r0 + 8) * SAB + c0 + 8];
                al[mt][0] = *(const uint32_t*)&Al[r0 * SAB + c0];
                al[mt][1] = *(const uint32_t*)&Al[(r0 + 8) * SAB + c0];
                al[mt][2] = *(const uint32_t*)&Al[r0 * SAB + c0 + 8];
                al[mt][3] = *(const uint32_t*)&Al[(r0 + 8) * SAB + c0 + 8];
            }
#pragma unroll
            for (int nt = 0; nt < 8; nt++) {
                int n0 = (warp_n * 64 + nt * 8 + g) * SAB + c0;
                uint32_t bh0 = *(const uint32_t*)&Bh[n0];
                uint32_t bh1 = *(const uint32_t*)&Bh[n0 + 8];
                uint32_t bl0 = *(const uint32_t*)&Bl[n0];
                uint32_t bl1 = *(const uint32_t*)&Bl[n0 + 8];
#pragma unroll
                for (int mt = 0; mt < 2; mt++) {
                    mma_bf16(acc[mt][nt], ah[mt], bh0, bh1);
                    mma_bf16(acc[mt][nt], ah[mt], bl0, bl1);
                    mma_bf16(acc[mt][nt], al[mt], bh0, bh1);
                }
            }
        }
        __syncthreads();
    }

    if (!ln_mode) {
#pragma unroll
        for (int mt = 0; mt < 2; mt++) {
            int r0 = bm0 + warp_m * 32 + mt * 16 + g;
#pragma unroll
            for (int nt = 0; nt < 8; nt++) {
                int c0 = bn0 + warp_n * 64 + nt * 8 + tg * 2;
                float b0 = bias[c0], b1 = bias[c0 + 1];
                float v0 = acc[mt][nt][0] + b0;
                float v1 = acc[mt][nt][1] + b1;
                float v2 = acc[mt][nt][2] + b0;
                float v3 = acc[mt][nt][3] + b1;
                if (relu) {
                    v0 = fmaxf(v0, 0.0f); v1 = fmaxf(v1, 0.0f);
                    v2 = fmaxf(v2, 0.0f); v3 = fmaxf(v3, 0.0f);
                }
                if (Cf) {
                    *(float2*)(Cf + (size_t)r0 * N + c0)       = make_float2(v0, v1);
                    *(float2*)(Cf + (size_t)(r0 + 8) * N + c0) = make_float2(v2, v3);
                }
                if (Ch) {
                    size_t o0 = (size_t)r0 * N + c0;
                    size_t o1 = (size_t)(r0 + 8) * N + c0;
                    *(uint32_t*)(Ch + o0) = packsplit_h(v0, v1);
                    *(uint32_t*)(Cl + o0) = packsplit_l(v0, v1);
                    *(uint32_t*)(Ch + o1) = packsplit_h(v2, v3);
                    *(uint32_t*)(Cl + o1) = packsplit_l(v2, v3);
                }
            }
        }
        return;
    }

    float* pS = (float*)smbuf;
    float* pQ = pS + 256;

#pragma unroll
    for (int mt = 0; mt < 2; mt++) {
#pragma unroll
        for (int half = 0; half < 2; half++) {
            int rl = warp_m * 32 + mt * 16 + g + half * 8;
            float s = 0.0f, q = 0.0f;
#pragma unroll
            for (int nt = 0; nt < 8; nt++) {
                int c0 = warp_n * 64 + nt * 8 + tg * 2;
                float2 rv = *(const float2*)(resid + (size_t)(bm0 + rl) * 128 + c0);
                float v0 = acc[mt][nt][2 * half]     + bias[c0]     + rv.x;
                float v1 = acc[mt][nt][2 * half + 1] + bias[c0 + 1] + rv.y;
                acc[mt][nt][2 * half]     = v0;
                acc[mt][nt][2 * half + 1] = v1;
                s += v0 + v1;
                q += v0 * v0 + v1 * v1;
            }
            s += __shfl_xor_sync(0xffffffffu, s, 1);
            q += __shfl_xor_sync(0xffffffffu, q, 1);
            s += __shfl_xor_sync(0xffffffffu, s, 2);
            q += __shfl_xor_sync(0xffffffffu, q, 2);
            if (tg == 0) {
                pS[rl * 2 + warp_n] = s;
                pQ[rl * 2 + warp_n] = q;
            }
        }
    }
    __syncthreads();

#pragma unroll
    for (int mt = 0; mt < 2; mt++) {
#pragma unroll
        for (int half = 0; half < 2; half++) {
            int rl = warp_m * 32 + mt * 16 + g + half * 8;
            float s = pS[rl * 2] + pS[rl * 2 + 1];
            float q = pQ[rl * 2] + pQ[rl * 2 + 1];
            float mu = s * (1.0f / 128.0f);
            float var = q * (1.0f / 128.0f) - mu * mu;
            float inv = rsqrtf(var + EPSV);
            size_t rbase = (size_t)(bm0 + rl) * 128;
#pragma unroll
            for (int nt = 0; nt < 8; nt++) {
                int c0 = warp_n * 64 + nt * 8 + tg * 2;
                float v0 = (acc[mt][nt][2 * half]     - mu) * inv * lng[c0]     + lnb[c0];
                float v1 = (acc[mt][nt][2 * half + 1] - mu) * inv * lng[c0 + 1] + lnb[c0 + 1];
                *(float2*)(Cf + rbase + c0) = make_float2(v0, v1);
                *(uint32_t*)(Ch + rbase + c0) = packsplit_h(v0, v1);
                *(uint32_t*)(Cl + rbase + c0) = packsplit_l(v0, v1);
            }
        }
    }
}

// ---------------- weight split+transpose kernels ---------------------------------
__global__ void wsplit_sq_kernel(const float* __restrict__ wq, const float* __restrict__ wk,
                                 const float* __restrict__ wv, const float* __restrict__ wo,
                                 const float* __restrict__ bq, const float* __restrict__ bk,
                                 const float* __restrict__ bv)
{
    int idx = blockIdx.x * blockDim.x + threadIdx.x;
    if (idx < L_ * 384) {
        int l = idx / 384, j = idx % 384;
        float v = (j < 128) ? bq[l * 128 + j] :
                  (j < 256) ? bk[l * 128 + j - 128] : bv[l * 128 + j - 256];
        d_bqkv[idx] = v;
    }
    if (idx >= L_ * 4 * 16384) return;
    int type = idx / (L_ * 16384);
    int rem  = idx % (L_ * 16384);
    int l    = rem / 16384;
    int kn   = rem % 16384;
    int k = kn >> 7, n = kn & 127;
    const float* src = (type == 0) ? wq : (type == 1) ? wk : (type == 2) ? wv : wo;
    float v = src[l * 16384 + k * 128 + n];
    __nv_bfloat16 h, lo;
    bf16split(v, h, lo);
    int off = (type < 3) ? (l * 49152 + type * 16384 + n * 128 + k)
                         : (147456 + l * 16384 + n * 128 + k);
    d_wh[off] = h; d_wl[off] = lo;
}

__global__ void wsplit_ff_kernel(const float* __restrict__ f1, const float* __restrict__ f2)
{
    int idx = blockIdx.x * blockDim.x + threadIdx.x;
    if (idx >= 2 * L_ * 65536) return;
    float v; int off;
    if (idx < L_ * 65536) {
        int l = idx / 65536, kn = idx % 65536;
        int k = kn >> 9, n = kn & 511;
        v = f1[l * 65536 + k * 512 + n];
        off = 196608 + l * 65536 + n * 128 + k;
    } else {
        int j = idx - L_ * 65536;
        int l = j / 65536, kn = j % 65536;
        int k = kn >> 7, n = kn & 127;
        v = f2[l * 65536 + k * 128 + n];
        off = 393216 + l * 65536 + n * 512 + k;
    }
    __nv_bfloat16 h, lo;
    bf16split(v, h, lo);
    d_wh[off] = h; d_wl[off] = lo;
}

// ---------------- hist projection + positional encoding --------------------------
__global__ void hist_pe_kernel(const float* __restrict__ feat,
                               const float* __restrict__ hw,
                               const float* __restrict__ hb)
{
    int idx = blockIdx.x * blockDim.x + threadIdx.x;
    if (idx >= R_ * D_) return;
    int row = idx >> 7;
    int d   = idx & 127;
    int t   = row & (T_ - 1);
    const float* f = feat + (size_t)row * 3;
    float xv = fmaf(f[0], hw[d],
               fmaf(f[1], hw[D_ + d],
               fmaf(f[2], hw[2 * D_ + d], hb[d])));
    d_x[idx] = xv;
    int j2 = d & ~1;
    float ang = (float)t * __expf(-9.210340371976184f * (float)j2 / 128.0f);
    float pe = (d & 1) ? __cosf(ang) : __sinf(ang);
    float oe = xv + pe;
    d_oute[idx] = oe;
    __nv_bfloat16 h, l;
    bf16split(oe, h, l);
    d_oute_h[idx] = h; d_oute_l[idx] = l;
}

// ---------------- attention per (b,n,h) ------------------------------------------
__global__ __launch_bounds__(128)
void attn_kernel()
{
    int blk = blockIdx.x;
    int h   = blk % H_;
    int bn  = blk / H_;
    const float* base = d_qkv + (size_t)bn * T_ * 384;

    __shared__ float Ks[T_][DH_];
    __shared__ float Vs[T_][DH_];
    int tid = threadIdx.x;
    for (int i = tid; i < T_ * DH_; i += 128) {
        int r = i >> 4, c = i & 15;
        Ks[r][c] = base[(size_t)r * 384 + 128 + h * DH_ + c];
        Vs[r][c] = base[(size_t)r * 384 + 256 + h * DH_ + c];
    }
    __syncthreads();

    const float* qrow = base + (size_t)tid * 384 + h * DH_;
    const float scale = 0.25f;
    float qr[DH_];
#pragma unroll
    for (int d = 0; d < DH_; d++) qr[d] = qrow[d] * scale;

    float m = -INFINITY, l = 0.0f;
    float acc[DH_];
#pragma unroll
    for (int d = 0; d < DH_; d++) acc[d] = 0.0f;

    for (int kk = 0; kk < T_; kk++) {
        float sc = 0.0f;
#pragma unroll
        for (int d = 0; d < DH_; d++) sc = fmaf(qr[d], Ks[kk][d], sc);
        float mn = fmaxf(m, sc);
        float corr = __expf(m - mn);
        float p = __expf(sc - mn);
        l = l * corr + p;
#pragma unroll
        for (int d = 0; d < DH_; d++) acc[d] = fmaf(acc[d], corr, p * Vs[kk][d]);
        m = mn;
    }
    float inv = 1.0f / l;
    size_t rowoff = (size_t)bn * T_ * D_ + (size_t)tid * D_ + h * DH_;
#pragma unroll
    for (int d = 0; d < DH_; d += 2) {
        float o0 = acc[d] * inv;
        float o1 = acc[d + 1] * inv;
        *(uint32_t*)(d_oh + rowoff + d) = packsplit_h(o0, o1);
        *(uint32_t*)(d_ol + rowoff + d) = packsplit_l(o0, o1);
    }
}

// ---------------- sdot + zero ----------------------------------------------------
__global__ void sdot_kernel()
{
    int gid = blockIdx.x * blockDim.x + threadIdx.x;
    int warp = gid >> 5;
    int lane = threadIdx.x & 31;
    if (gid < B_ * NN_) d_g[gid] = 0.0f;
    if (gid < 2) d_stats[gid] = 0.0;
    if (warp >= R_) return;
    size_t base = (size_t)warp * D_ + lane * 4;
    float4 w4 = *(const float4*)(d_oute + base);
    float4 x4 = *(const float4*)(d_x + base);
    float dt = w4.x * x4.x + w4.y * x4.y + w4.z * x4.z + w4.w * x4.w;
#pragma unroll
    for (int o = 16; o; o >>= 1) dt += __shfl_xor_sync(0xffffffffu, dt, o);
    if (lane == 0) {
        int b = warp / (NA_ * T_);
        int rem = warp % (NA_ * T_);
        int n = rem / T_;
        int t = rem % T_;
        d_s[b * NN_ + t * NA_ + n] = dt;
    }
}

// ---------------- edge aggregation ----------------------------------------------
__global__ void edge_kernel(const int* __restrict__ ei, const float* __restrict__ ew)
{
    int gid = blockIdx.x * blockDim.x + threadIdx.x;
    if (gid >= B_ * E_) return;
    int b = gid >> 16;
    int e = gid & (E_ - 1);
    const int* eb = ei + ((size_t)b << 17);
    int src = eb[e];
    int dst = eb[E_ + e];
    atomicAdd(&d_g[(b << 13) + dst], ew[((size_t)b << 16) + e] * d_s[(b << 13) + src]);
}

// ---------------- global batchnorm stats -----------------------------------------
__global__ void bnstats_kernel()
{
    double s = 0.0, sq = 0.0;
    for (int i = blockIdx.x * blockDim.x + threadIdx.x; i < B_ * NN_;
         i += gridDim.x * blockDim.x) {
        double v = (double)d_g[i];
        s += v; sq += v * v;
    }
#pragma unroll
    for (int o = 16; o; o >>= 1) {
        s  += __shfl_xor_sync(0xffffffffu, s, o);
        sq += __shfl_xor_sync(0xffffffffu, sq, o);
    }
    if ((threadIdx.x & 31) == 0) {
        atomicAdd(&d_stats[0], s);
        atomicAdd(&d_stats[1], sq);
    }
}

// ---------------- final outer product --------------------------------------------
__global__ void final_kernel(const float* __restrict__ bng, const float* __restrict__ bnb,
                             const float* __restrict__ lw, const float* __restrict__ lb,
                             float* __restrict__ out)
{
    int idx = blockIdx.x * blockDim.x + threadIdx.x;
    if (idx >= R_ * D_) return;
    int d   = idx & 127;
    int row = idx >> 7;
    int t   = row & 127;
    int bn  = row >> 7;
    int b   = bn >> 6;
    int n   = bn & 63;
    double mu  = d_stats[0] * (1.0 / 32768.0);
    double var = d_stats[1] * (1.0 / 32768.0) - mu * mu;
    float inv = rsqrtf((float)var + EPSV);
    float gval = d_g[b * NN_ + t * NA_ + n];
    float ghat = ((gval - (float)mu) * inv) * bng[0] + bnb[0];
    out[idx] = ghat * lw[d] + lb[d];
}

// ---------------- launcher -------------------------------------------------------
extern "C" void kernel_launch(void* const* d_in, const int* in_sizes, int n_in,
                              void* d_out, int out_size)
{
    const float* feat    = (const float*)d_in[0];
    const int*   eindex  = (const int*)  d_in[1];
    const float* eweight = (const float*)d_in[2];
    const float* hist_w  = (const float*)d_in[3];
    const float* hist_b  = (const float*)d_in[4];
    const float* wq      = (const float*)d_in[5];
    const float* bq      = (const float*)d_in[6];
    const float* wk      = (const float*)d_in[7];
    const float* bk      = (const float*)d_in[8];
    const float* wv      = (const float*)d_in[9];
    const float* bv      = (const float*)d_in[10];
    const float* wo      = (const float*)d_in[11];
    const float* bo      = (const float*)d_in[12];
    const float* ln1g    = (const float*)d_in[13];
    const float* ln1b    = (const float*)d_in[14];
    const float* fw1     = (const float*)d_in[15];
    const float* fb1     = (const float*)d_in[16];
    const float* fw2     = (const float*)d_in[17];
    const float* fb2     = (const float*)d_in[18];
    const float* ln2g    = (const float*)d_in[19];
    const float* ln2b    = (const float*)d_in[20];
    const float* bng     = (const float*)d_in[21];
    const float* bnb     = (const float*)d_in[22];
    const float* linw    = (const float*)d_in[23];
    const float* linb    = (const float*)d_in[24];
    float* out = (float*)d_out;

    float* pqkv = nullptr; cudaGetSymbolAddress((void**)&pqkv, d_qkv);
    float* poute = nullptr; cudaGetSymbolAddress((void**)&poute, d_oute);
    float* ph1  = nullptr; cudaGetSymbolAddress((void**)&ph1, d_h1);
    float* pbqkv = nullptr; cudaGetSymbolAddress((void**)&pbqkv, d_bqkv);

    __nv_bfloat16 *poute_h, *poute_l, *poh, *pol, *ph1h, *ph1l, *pffh, *pffl, *pwh, *pwl;
    cudaGetSymbolAddress((void**)&poute_h, d_oute_h);
    cudaGetSymbolAddress((void**)&poute_l, d_oute_l);
    cudaGetSymbolAddress((void**)&poh,  d_oh);
    cudaGetSymbolAddress((void**)&pol,  d_ol);
    cudaGetSymbolAddress((void**)&ph1h, d_h1h);
    cudaGetSymbolAddress((void**)&ph1l, d_h1l);
    cudaGetSymbolAddress((void**)&pffh, d_ffh);
    cudaGetSymbolAddress((void**)&pffl, d_ffl);
    cudaGetSymbolAddress((void**)&pwh,  d_wh);
    cudaGetSymbolAddress((void**)&pwl,  d_wl);

    cudaFuncSetAttribute(split_gemm_kernel,
                         cudaFuncAttributeMaxDynamicSharedMemorySize, GEMM_SMEM);
    cudaFuncSetAttribute(pgemm_kernel,
                         cudaFuncAttributeMaxDynamicSharedMemorySize, PG_SMEM);

    const int TPB = 256;

    // 0. weight split+transpose
    wsplit_sq_kernel<<<(L_ * 4 * 16384 + TPB - 1) / TPB, TPB>>>(wq, wk, wv, wo, bq, bk, bv);
    wsplit_ff_kernel<<<(2 * L_ * 65536 + TPB - 1) / TPB, TPB>>>(fw1, fw2);

    // 1. x + positional encoding
    hist_pe_kernel<<<(R_ * D_ + TPB - 1) / TPB, TPB>>>(feat, hist_w, hist_b);

    // 2. transformer layers
    for (int l = 0; l < L_; l++) {
        const __nv_bfloat16* wqkvh = pwh + l * 49152;
        const __nv_bfloat16* wqkvl = pwl + l * 49152;
        const __nv_bfloat16* woh = pwh + 147456 + l * 16384;
        const __nv_bfloat16* wol = pwl + 147456 + l * 16384;
        const __nv_bfloat16* f1h = pwh + 196608 + l * 65536;
        const __nv_bfloat16* f1l = pwl + 196608 + l * 65536;
        const __nv_bfloat16* f2h = pwh + 393216 + l * 65536;
        const __nv_bfloat16* f2l = pwl + 393216 + l * 65536;

        // fused QKV: N=384, MT=4 -> grid (3, 64)
        pgemm_kernel<<<dim3(3, 64), 256, PG_SMEM>>>(
            poute_h, poute_l, wqkvh, wqkvl, pbqkv + l * 384,
            pqkv, nullptr, nullptr, 384, 0, 0, nullptr, nullptr, nullptr, 4);

        attn_kernel<<<B_ * NA_ * H_, 128>>>();

        // O-proj + residual + LN1 -> h1, MT=1 -> grid (1, 256)
        pgemm_kernel<<<dim3(1, 256), 256, PG_SMEM>>>(
            poh, pol, woh, wol, bo + l * D_,
            ph1, ph1h, ph1l, D_, 0, 1, poute, ln1g + l * D_, ln1b + l * D_, 1);

        // FFN-1 (ReLU), MT=4 -> grid (4, 64)
        pgemm_kernel<<<dim3(4, 64), 256, PG_SMEM>>>(
            ph1h, ph1l, f1h, f1l, fb1 + l * DFF_,
            nullptr, pffh, pffl, DFF_, 1, 0, nullptr, nullptr, nullptr, 4);

        // FFN-2 (K=512) + residual + LN2 -> oute
        split_gemm_kernel<<<dim3(1, 256), 256, GEMM_SMEM>>>(
            pffh, pffl, f2h, f2l, fb2 + l * D_,
            poute, poute_h, poute_l, DFF_, D_, 0, 1, ph1, ln2g + l * D_, ln2b + l * D_);
    }

    // 3. scoring dot products (+ zero of d_g/d_stats)
    sdot_kernel<<<(R_ * 32 + TPB - 1) / TPB, TPB>>>();

    // 4. edge aggregation
    edge_kernel<<<(B_ * E_ + TPB - 1) / TPB, TPB>>>(eindex, eweight);

    // 5. global batchnorm stats + final outer product
    bnstats_kernel<<<64, TPB>>>();
    final_kernel<<<(R_ * D_ + TPB - 1) / TPB, TPB>>>(bng, bnb, linw, linb, out);
}

// round 8
// speedup vs baseline: 1.5735x; 1.0017x over previous
#include <cuda_runtime.h>
#include <cuda_bf16.h>
#include <cstdint>
#include <math.h>

// Problem constants
#define B_   4
#define NA_  64
#define T_   128
#define D_   128
#define H_   8
#define DH_  16
#define L_   3
#define DFF_ 512
#define E_   65536
#define NN_  (T_ * NA_)        // 8192
#define R_   (B_ * NA_ * T_)   // 32768 rows
#define EPSV 1e-5f

// ---------------- scratch (device globals) ---------------------------------------
__device__ __align__(256) float d_x   [R_ * D_];
__device__ __align__(256) float d_oute[R_ * D_];
__device__ __align__(256) float d_qkv [R_ * 384];
__device__ __align__(256) float d_h1  [R_ * D_];
__device__ __align__(256) float d_s   [B_ * NN_];
__device__ __align__(256) float d_g   [B_ * NN_];
__device__ double d_stats[2];

// bf16 split activations (hi / lo)
__device__ __align__(256) __nv_bfloat16 d_oute_h[R_ * D_];
__device__ __align__(256) __nv_bfloat16 d_oute_l[R_ * D_];
__device__ __align__(256) __nv_bfloat16 d_oh[R_ * D_];
__device__ __align__(256) __nv_bfloat16 d_ol[R_ * D_];
__device__ __align__(256) __nv_bfloat16 d_h1h[R_ * D_];
__device__ __align__(256) __nv_bfloat16 d_h1l[R_ * D_];
__device__ __align__(256) __nv_bfloat16 d_ffh[R_ * DFF_];
__device__ __align__(256) __nv_bfloat16 d_ffl[R_ * DFF_];

// bf16 split transposed weights ([N][K])
#define W_TOT 589824
__device__ __align__(256) __nv_bfloat16 d_wh[W_TOT];
__device__ __align__(256) __nv_bfloat16 d_wl[W_TOT];
__device__ __align__(256) float d_bqkv[L_ * 384];

// ---------------- helpers --------------------------------------------------------
__device__ __forceinline__ uint32_t smem_u32(const void* p) {
    uint32_t a;
    asm("{ .reg .u64 t; cvta.to.shared.u64 t, %1; cvt.u32.u64 %0, t; }" : "=r"(a) : "l"(p));
    return a;
}
__device__ __forceinline__ void cp16(uint32_t saddr, const void* gptr) {
    asm volatile("cp.async.cg.shared.global [%0], [%1], 16;" :: "r"(saddr), "l"(gptr));
}
#define CP_COMMIT() asm volatile("cp.async.commit_group;" ::: "memory")
#define CP_WAIT(n)  asm volatile("cp.async.wait_group %0;" :: "n"(n) : "memory")

#define LDSM_X4(r, addr) \
    asm volatile("ldmatrix.sync.aligned.m8n8.x4.shared.b16 {%0,%1,%2,%3}, [%4];" \
        : "=r"((r)[0]), "=r"((r)[1]), "=r"((r)[2]), "=r"((r)[3]) : "r"(addr))

__device__ __forceinline__ void bf16split(float v, __nv_bfloat16& h, __nv_bfloat16& l) {
    h = __float2bfloat16_rn(v);
    l = __float2bfloat16_rn(v - __bfloat162float(h));
}
__device__ __forceinline__ uint32_t packsplit_h(float v0, float v1) {
    __nv_bfloat16 h0 = __float2bfloat16_rn(v0);
    __nv_bfloat16 h1 = __float2bfloat16_rn(v1);
    return (uint32_t)__bfloat16_as_ushort(h0) | ((uint32_t)__bfloat16_as_ushort(h1) << 16);
}
__device__ __forceinline__ uint32_t packsplit_l(float v0, float v1) {
    __nv_bfloat16 h0 = __float2bfloat16_rn(v0);
    __nv_bfloat16 h1 = __float2bfloat16_rn(v1);
    __nv_bfloat16 l0 = __float2bfloat16_rn(v0 - __bfloat162float(h0));
    __nv_bfloat16 l1 = __float2bfloat16_rn(v1 - __bfloat162float(h1));
    return (uint32_t)__bfloat16_as_ushort(l0) | ((uint32_t)__bfloat16_as_ushort(l1) << 16);
}

__device__ __forceinline__ void mma_bf16(float* c, const uint32_t* a,
                                         uint32_t b0, uint32_t b1) {
    asm volatile(
        "mma.sync.aligned.m16n8k16.row.col.f32.bf16.bf16.f32 "
        "{%0,%1,%2,%3}, {%4,%5,%6,%7}, {%8,%9}, {%0,%1,%2,%3};"
        : "+f"(c[0]), "+f"(c[1]), "+f"(c[2]), "+f"(c[3])
        : "r"(a[0]), "r"(a[1]), "r"(a[2]), "r"(a[3]), "r"(b0), "r"(b1));
}

// ================= persistent-B GEMM (K=128): C = A @ B^T + bias ================
#define SAB 40
#define SBB 136
#define PG_B_ELEMS (128 * SBB)
#define PG_A_ELEMS (128 * SAB)
#define PG_A_OFF   (2 * PG_B_ELEMS)
#define PG_LN_OFF  (PG_A_OFF + 4 * PG_A_ELEMS)
#define PG_SMEM    ((PG_LN_OFF) * 2 + 2048)     // 112640 bytes

__global__ void __launch_bounds__(256, 2)
pgemm_kernel(const __nv_bfloat16* __restrict__ Ahg, const __nv_bfloat16* __restrict__ Alg,
             const __nv_bfloat16* __restrict__ Bhg, const __nv_bfloat16* __restrict__ Blg,
             const float* __restrict__ bias,
             float* __restrict__ Cf,
             __nv_bfloat16* __restrict__ Ch, __nv_bfloat16* __restrict__ Cl,
             int N, int relu, int ln_mode,
             const float* __restrict__ resid,
             const float* __restrict__ lng, const float* __restrict__ lnb,
             int MT)
{
    extern __shared__ uint16_t sm[];
    uint16_t* Bh = sm;
    uint16_t* Bl = sm + PG_B_ELEMS;
    uint16_t* Ast = sm + PG_A_OFF;
    float* pS = (float*)(sm + PG_LN_OFF);
    float* pQ = pS + 256;

    int tid  = threadIdx.x;
    int wid  = tid >> 5;
    int lane = tid & 31;
    int g    = lane >> 2;
    int tg   = lane & 3;
    int lr   = lane & 7;
    int seg  = lane >> 3;
    int warp_m = wid & 3;
    int warp_n = wid >> 2;
    int bn0 = blockIdx.x * 128;
    int bm0 = blockIdx.y * (MT << 7);

    // ---- load full B tile (hi+lo) via cp.async ----
    {
        const uint16_t* bh = (const uint16_t*)Bhg + (size_t)bn0 * 128;
        const uint16_t* bl = (const uint16_t*)Blg + (size_t)bn0 * 128;
#pragma unroll
        for (int it = 0; it < 8; it++) {
            int idx = it * 256 + tid;
            int row = idx >> 4, ch = idx & 15;
            cp16(smem_u32(Bh + row * SBB + ch * 8), bh + row * 128 + ch * 8);
            cp16(smem_u32(Bl + row * SBB + ch * 8), bl + row * 128 + ch * 8);
        }
    }

    int lrow = tid >> 2;
    int lch  = tid & 3;

    const uint16_t* ahg = (const uint16_t*)Ahg;
    const uint16_t* alg = (const uint16_t*)Alg;

    int NC = MT << 2;

    {
        uint16_t* dh = Ast;
        uint16_t* dl = Ast + PG_A_ELEMS;
        const uint16_t* ah = ahg + (size_t)bm0 * 128;
        const uint16_t* al = alg + (size_t)bm0 * 128;
#pragma unroll
        for (int it = 0; it < 2; it++) {
            int row = lrow + it * 64;
            cp16(smem_u32(dh + row * SAB + lch * 8), ah + (size_t)row * 128 + lch * 8);
            cp16(smem_u32(dl + row * SAB + lch * 8), al + (size_t)row * 128 + lch * 8);
        }
    }
    CP_COMMIT();

    float acc[2][8][4];
#pragma unroll
    for (int mt = 0; mt < 2; mt++)
#pragma unroll
        for (int nt = 0; nt < 8; nt++)
#pragma unroll
            for (int j = 0; j < 4; j++) acc[mt][nt][j] = 0.0f;

    for (int c = 0; c < NC; c++) {
        if (c + 1 < NC) {
            int nmt = (c + 1) >> 2, nkc = (c + 1) & 3;
            uint16_t* dh = Ast + ((c + 1) & 1) * (2 * PG_A_ELEMS);
            uint16_t* dl = dh + PG_A_ELEMS;
            const uint16_t* ah = ahg + (size_t)(bm0 + (nmt << 7)) * 128 + nkc * 32;
            const uint16_t* al = alg + (size_t)(bm0 + (nmt << 7)) * 128 + nkc * 32;
#pragma unroll
            for (int it = 0; it < 2; it++) {
                int row = lrow + it * 64;
                cp16(smem_u32(dh + row * SAB + lch * 8), ah + (size_t)row * 128 + lch * 8);
                cp16(smem_u32(dl + row * SAB + lch * 8), al + (size_t)row * 128 + lch * 8);
            }
            CP_COMMIT();
            CP_WAIT(1);
        } else {
            CP_WAIT(0);
        }
        __syncthreads();

        uint16_t* Ah = Ast + (c & 1) * (2 * PG_A_ELEMS);
        uint16_t* Al = Ah + PG_A_ELEMS;
        int kc = c & 3;

#pragma unroll
        for (int ks = 0; ks < 2; ks++) {
            int ac0 = ks * 16 + (seg >> 1) * 8;
            int bc0 = kc * 32 + ks * 16 + (seg & 1) * 8;
            uint32_t ahf[2][4], alf[2][4];
#pragma unroll
            for (int mt = 0; mt < 2; mt++) {
                int row = warp_m * 32 + mt * 16 + lr + (seg & 1) * 8;
                LDSM_X4(ahf[mt], smem_u32(&Ah[row * SAB + ac0]));
                LDSM_X4(alf[mt], smem_u32(&Al[row * SAB + ac0]));
            }
#pragma unroll
            for (int p = 0; p < 4; p++) {
                int row = warp_n * 64 + p * 16 + lr + (seg >> 1) * 8;
                uint32_t bhf[4], blf[4];
                LDSM_X4(bhf, smem_u32(&Bh[row * SBB + bc0]));
                LDSM_X4(blf, smem_u32(&Bl[row * SBB + bc0]));
#pragma unroll
                for (int hf = 0; hf < 2; hf++) {
                    int nt = 2 * p + hf;
#pragma unroll
                    for (int mt = 0; mt < 2; mt++) {
                        mma_bf16(acc[mt][nt], ahf[mt], bhf[2 * hf], bhf[2 * hf + 1]);
                        mma_bf16(acc[mt][nt], ahf[mt], blf[2 * hf], blf[2 * hf + 1]);
                        mma_bf16(acc[mt][nt], alf[mt], bhf[2 * hf], bhf[2 * hf + 1]);
                    }
                }
            }
        }

        if (kc == 3) {
            int mt_i = c >> 2;
            int rbm = bm0 + (mt_i << 7);
            if (!ln_mode) {
#pragma unroll
                for (int mt = 0; mt < 2; mt++) {
                    int r0 = rbm + warp_m * 32 + mt * 16 + g;
#pragma unroll
                    for (int nt = 0; nt < 8; nt++) {
                        int c0 = bn0 + warp_n * 64 + nt * 8 + tg * 2;
                        float b0 = bias[c0], b1 = bias[c0 + 1];
                        float v0 = acc[mt][nt][0] + b0;
                        float v1 = acc[mt][nt][1] + b1;
                        float v2 = acc[mt][nt][2] + b0;
                        float v3 = acc[mt][nt][3] + b1;
                        if (relu) {
                            v0 = fmaxf(v0, 0.0f); v1 = fmaxf(v1, 0.0f);
                            v2 = fmaxf(v2, 0.0f); v3 = fmaxf(v3, 0.0f);
                        }
                        if (Cf) {
                            *(float2*)(Cf + (size_t)r0 * N + c0)       = make_float2(v0, v1);
                            *(float2*)(Cf + (size_t)(r0 + 8) * N + c0) = make_float2(v2, v3);
                        }
                        if (Ch) {
                            size_t o0 = (size_t)r0 * N + c0;
                            size_t o1 = (size_t)(r0 + 8) * N + c0;
                            *(uint32_t*)(Ch + o0) = packsplit_h(v0, v1);
                            *(uint32_t*)(Cl + o0) = packsplit_l(v0, v1);
                            *(uint32_t*)(Ch + o1) = packsplit_h(v2, v3);
                            *(uint32_t*)(Cl + o1) = packsplit_l(v2, v3);
                        }
                    }
                }
            } else {
#pragma unroll
                for (int mt = 0; mt < 2; mt++) {
#pragma unroll
                    for (int half = 0; half < 2; half++) {
                        int rl = warp_m * 32 + mt * 16 + g + half * 8;
                        float s = 0.0f, q = 0.0f;
#pragma unroll
                        for (int nt = 0; nt < 8; nt++) {
                            int c0 = warp_n * 64 + nt * 8 + tg * 2;
                            float2 rv = *(const float2*)(resid + (size_t)(rbm + rl) * 128 + c0);
                            float v0 = acc[mt][nt][2 * half]     + bias[c0]     + rv.x;
                            float v1 = acc[mt][nt][2 * half + 1] + bias[c0 + 1] + rv.y;
                            acc[mt][nt][2 * half]     = v0;
                            acc[mt][nt][2 * half + 1] = v1;
                            s += v0 + v1;
                            q += v0 * v0 + v1 * v1;
                        }
                        s += __shfl_xor_sync(0xffffffffu, s, 1);
                        q += __shfl_xor_sync(0xffffffffu, q, 1);
                        s += __shfl_xor_sync(0xffffffffu, s, 2);
                        q += __shfl_xor_sync(0xffffffffu, q, 2);
                        if (tg == 0) {
                            pS[rl * 2 + warp_n] = s;
                            pQ[rl * 2 + warp_n] = q;
                        }
                    }
                }
                __syncthreads();
#pragma unroll
                for (int mt = 0; mt < 2; mt++) {
#pragma unroll
                    for (int half = 0; half < 2; half++) {
                        int rl = warp_m * 32 + mt * 16 + g + half * 8;
                        float s = pS[rl * 2] + pS[rl * 2 + 1];
                        float q = pQ[rl * 2] + pQ[rl * 2 + 1];
                        float mu = s * (1.0f / 128.0f);
                        float var = q * (1.0f / 128.0f) - mu * mu;
                        float inv = rsqrtf(var + EPSV);
                        size_t rbase = (size_t)(rbm + rl) * 128;
#pragma unroll
                        for (int nt = 0; nt < 8; nt++) {
                            int c0 = warp_n * 64 + nt * 8 + tg * 2;
                            float v0 = (acc[mt][nt][2 * half]     - mu) * inv * lng[c0]     + lnb[c0];
                            float v1 = (acc[mt][nt][2 * half + 1] - mu) * inv * lng[c0 + 1] + lnb[c0 + 1];
                            *(float2*)(Cf + rbase + c0) = make_float2(v0, v1);
                            *(uint32_t*)(Ch + rbase + c0) = packsplit_h(v0, v1);
                            *(uint32_t*)(Cl + rbase + c0) = packsplit_l(v0, v1);
                        }
                    }
                }
            }
#pragma unroll
            for (int mt = 0; mt < 2; mt++)
#pragma unroll
                for (int nt = 0; nt < 8; nt++)
#pragma unroll
                    for (int j = 0; j < 4; j++) acc[mt][nt][j] = 0.0f;
        }
        __syncthreads();
    }
}

// ---------------- chunked split-bf16 GEMM (for K=512 FF2) ------------------------
#define ARR_ELEMS (128 * SAB)
#define STAGE_ELEMS (4 * ARR_ELEMS)
#define GEMM_SMEM (2 * STAGE_ELEMS * 2)

__global__ void __launch_bounds__(256, 2)
split_gemm_kernel(const __nv_bfloat16* __restrict__ Ahg, const __nv_bfloat16* __restrict__ Alg,
                  const __nv_bfloat16* __restrict__ Bhg, const __nv_bfloat16* __restrict__ Blg,
                  const float* __restrict__ bias,
                  float* __restrict__ Cf,
                  __nv_bfloat16* __restrict__ Ch, __nv_bfloat16* __restrict__ Cl,
                  int K, int N, int relu,
                  int ln_mode,
                  const float* __restrict__ resid,
                  const float* __restrict__ lng, const float* __restrict__ lnb)
{
    extern __shared__ uint16_t smbuf[];

    int tid  = threadIdx.x;
    int wid  = tid >> 5;
    int lane = tid & 31;
    int g    = lane >> 2;
    int tg   = lane & 3;
    int lr   = lane & 7;
    int seg  = lane >> 3;
    int warp_m = wid & 3;
    int warp_n = wid >> 2;
    int bm0 = blockIdx.y * 128;
    int bn0 = blockIdx.x * 128;

    const __nv_bfloat16* gbase[4];
    gbase[0] = Ahg + (size_t)bm0 * K;
    gbase[1] = Alg + (size_t)bm0 * K;
    gbase[2] = Bhg + (size_t)bn0 * K;
    gbase[3] = Blg + (size_t)bn0 * K;

    int lrow = tid >> 2;
    int lch  = tid & 3;

    float acc[2][8][4];
#pragma unroll
    for (int mt = 0; mt < 2; mt++)
#pragma unroll
        for (int nt = 0; nt < 8; nt++)
#pragma unroll
            for (int j = 0; j < 4; j++) acc[mt][nt][j] = 0.0f;

    int nch = K >> 5;

    {
        uint16_t* st = smbuf;
#pragma unroll
        for (int arr = 0; arr < 4; arr++) {
            uint16_t* da = st + arr * ARR_ELEMS;
#pragma unroll
            for (int it = 0; it < 2; it++) {
                int row = lrow + it * 64;
                cp16(smem_u32(da + row * SAB + lch * 8),
                     gbase[arr] + (size_t)row * K + lch * 8);
            }
        }
    }
    CP_COMMIT();

    for (int kc = 0; kc < nch; kc++) {
        if (kc + 1 < nch) {
            uint16_t* st = smbuf + ((kc + 1) & 1) * STAGE_ELEMS;
            int koff = (kc + 1) * 32;
#pragma unroll
            for (int arr = 0; arr < 4; arr++) {
                uint16_t* da = st + arr * ARR_ELEMS;
#pragma unroll
                for (int it = 0; it < 2; it++) {
                    int row = lrow + it * 64;
                    cp16(smem_u32(da + row * SAB + lch * 8),
                         gbase[arr] + (size_t)row * K + koff + lch * 8);
                }
            }
            CP_COMMIT();
            CP_WAIT(1);
        } else {
            CP_WAIT(0);
        }
        __syncthreads();

        uint16_t* st = smbuf + (kc & 1) * STAGE_ELEMS;
        uint16_t* Ah = st;
        uint16_t* Al = st + ARR_ELEMS;
        uint16_t* Bh = st + 2 * ARR_ELEMS;
        uint16_t* Bl = st + 3 * ARR_ELEMS;

#pragma unroll
        for (int ks = 0; ks < 2; ks++) {
            int ac0 = ks * 16 + (seg >> 1) * 8;
            int bc0 = ks * 16 + (seg & 1) * 8;
            uint32_t ahf[2][4], alf[2][4];
#pragma unroll
            for (int mt = 0; mt < 2; mt++) {
                int row = warp_m * 32 + mt * 16 + lr + (seg & 1) * 8;
                LDSM_X4(ahf[mt], smem_u32(&Ah[row * SAB + ac0]));
                LDSM_X4(alf[mt], smem_u32(&Al[row * SAB + ac0]));
            }
#pragma unroll
            for (int p = 0; p < 4; p++) {
                int row = warp_n * 64 + p * 16 + lr + (seg >> 1) * 8;
                uint32_t bhf[4], blf[4];
                LDSM_X4(bhf, smem_u32(&Bh[row * SAB + bc0]));
                LDSM_X4(blf, smem_u32(&Bl[row * SAB + bc0]));
#pragma unroll
                for (int hf = 0; hf < 2; hf++) {
                    int nt = 2 * p + hf;
#pragma unroll
                    for (int mt = 0; mt < 2; mt++) {
                        mma_bf16(acc[mt][nt], ahf[mt], bhf[2 * hf], bhf[2 * hf + 1]);
                        mma_bf16(acc[mt][nt], ahf[mt], blf[2 * hf], blf[2 * hf + 1]);
                        mma_bf16(acc[mt][nt], alf[mt], bhf[2 * hf], bhf[2 * hf + 1]);
                    }
                }
            }
        }
        __syncthreads();
    }

    if (!ln_mode) {
#pragma unroll
        for (int mt = 0; mt < 2; mt++) {
            int r0 = bm0 + warp_m * 32 + mt * 16 + g;
#pragma unroll
            for (int nt = 0; nt < 8; nt++) {
                int c0 = bn0 + warp_n * 64 + nt * 8 + tg * 2;
                float b0 = bias[c0], b1 = bias[c0 + 1];
                float v0 = acc[mt][nt][0] + b0;
                float v1 = acc[mt][nt][1] + b1;
                float v2 = acc[mt][nt][2] + b0;
                float v3 = acc[mt][nt][3] + b1;
                if (relu) {
                    v0 = fmaxf(v0, 0.0f); v1 = fmaxf(v1, 0.0f);
                    v2 = fmaxf(v2, 0.0f); v3 = fmaxf(v3, 0.0f);
                }
                if (Cf) {
                    *(float2*)(Cf + (size_t)r0 * N + c0)       = make_float2(v0, v1);
                    *(float2*)(Cf + (size_t)(r0 + 8) * N + c0) = make_float2(v2, v3);
                }
                if (Ch) {
                    size_t o0 = (size_t)r0 * N + c0;
                    size_t o1 = (size_t)(r0 + 8) * N + c0;
                    *(uint32_t*)(Ch + o0) = packsplit_h(v0, v1);
                    *(uint32_t*)(Cl + o0) = packsplit_l(v0, v1);
                    *(uint32_t*)(Ch + o1) = packsplit_h(v2, v3);
                    *(uint32_t*)(Cl + o1) = packsplit_l(v2, v3);
                }
            }
        }
        return;
    }

    float* pS = (float*)smbuf;
    float* pQ = pS + 256;

#pragma unroll
    for (int mt = 0; mt < 2; mt++) {
#pragma unroll
        for (int half = 0; half < 2; half++) {
            int rl = warp_m * 32 + mt * 16 + g + half * 8;
            float s = 0.0f, q = 0.0f;
#pragma unroll
            for (int nt = 0; nt < 8; nt++) {
                int c0 = warp_n * 64 + nt * 8 + tg * 2;
                float2 rv = *(const float2*)(resid + (size_t)(bm0 + rl) * 128 + c0);
                float v0 = acc[mt][nt][2 * half]     + bias[c0]     + rv.x;
                float v1 = acc[mt][nt][2 * half + 1] + bias[c0 + 1] + rv.y;
                acc[mt][nt][2 * half]     = v0;
                acc[mt][nt][2 * half + 1] = v1;
                s += v0 + v1;
                q += v0 * v0 + v1 * v1;
            }
            s += __shfl_xor_sync(0xffffffffu, s, 1);
            q += __shfl_xor_sync(0xffffffffu, q, 1);
            s += __shfl_xor_sync(0xffffffffu, s, 2);
            q += __shfl_xor_sync(0xffffffffu, q, 2);
            if (tg == 0) {
                pS[rl * 2 + warp_n] = s;
                pQ[rl * 2 + warp_n] = q;
            }
        }
    }
    __syncthreads();

#pragma unroll
    for (int mt = 0; mt < 2; mt++) {
#pragma unroll
        for (int half = 0; half < 2; half++) {
            int rl = warp_m * 32 + mt * 16 + g + half * 8;
            float s = pS[rl * 2] + pS[rl * 2 + 1];
            float q = pQ[rl * 2] + pQ[rl * 2 + 1];
            float mu = s * (1.0f / 128.0f);
            float var = q * (1.0f / 128.0f) - mu * mu;
            float inv = rsqrtf(var + EPSV);
            size_t rbase = (size_t)(bm0 + rl) * 128;
#pragma unroll
            for (int nt = 0; nt < 8; nt++) {
                int c0 = warp_n * 64 + nt * 8 + tg * 2;
                float v0 = (acc[mt][nt][2 * half]     - mu) * inv * lng[c0]     + lnb[c0];
                float v1 = (acc[mt][nt][2 * half + 1] - mu) * inv * lng[c0 + 1] + lnb[c0 + 1];
                *(float2*)(Cf + rbase + c0) = make_float2(v0, v1);
                *(uint32_t*)(Ch + rbase + c0) = packsplit_h(v0, v1);
                *(uint32_t*)(Cl + rbase + c0) = packsplit_l(v0, v1);
            }
        }
    }
}

// ---------------- weight split+transpose kernels ---------------------------------
__global__ void wsplit_sq_kernel(const float* __restrict__ wq, const float* __restrict__ wk,
                                 const float* __restrict__ wv, const float* __restrict__ wo,
                                 const float* __restrict__ bq, const float* __restrict__ bk,
                                 const float* __restrict__ bv)
{
    int idx = blockIdx.x * blockDim.x + threadIdx.x;
    if (idx < L_ * 384) {
        int l = idx / 384, j = idx % 384;
        float v = (j < 128) ? bq[l * 128 + j] :
                  (j < 256) ? bk[l * 128 + j - 128] : bv[l * 128 + j - 256];
        d_bqkv[idx] = v;
    }
    if (idx >= L_ * 4 * 16384) return;
    int type = idx / (L_ * 16384);
    int rem  = idx % (L_ * 16384);
    int l    = rem / 16384;
    int kn   = rem % 16384;
    int k = kn >> 7, n = kn & 127;
    const float* src = (type == 0) ? wq : (type == 1) ? wk : (type == 2) ? wv : wo;
    float v = src[l * 16384 + k * 128 + n];
    __nv_bfloat16 h, lo;
    bf16split(v, h, lo);
    int off = (type < 3) ? (l * 49152 + type * 16384 + n * 128 + k)
                         : (147456 + l * 16384 + n * 128 + k);
    d_wh[off] = h; d_wl[off] = lo;
}

__global__ void wsplit_ff_kernel(const float* __restrict__ f1, const float* __restrict__ f2)
{
    int idx = blockIdx.x * blockDim.x + threadIdx.x;
    if (idx >= 2 * L_ * 65536) return;
    float v; int off;
    if (idx < L_ * 65536) {
        int l = idx / 65536, kn = idx % 65536;
        int k = kn >> 9, n = kn & 511;
        v = f1[l * 65536 + k * 512 + n];
        off = 196608 + l * 65536 + n * 128 + k;
    } else {
        int j = idx - L_ * 65536;
        int l = j / 65536, kn = j % 65536;
        int k = kn >> 7, n = kn & 127;
        v = f2[l * 65536 + k * 128 + n];
        off = 393216 + l * 65536 + n * 512 + k;
    }
    __nv_bfloat16 h, lo;
    bf16split(v, h, lo);
    d_wh[off] = h; d_wl[off] = lo;
}

// ---------------- hist projection + positional encoding --------------------------
__global__ void hist_pe_kernel(const float* __restrict__ feat,
                               const float* __restrict__ hw,
                               const float* __restrict__ hb)
{
    int idx = blockIdx.x * blockDim.x + threadIdx.x;
    if (idx >= R_ * D_) return;
    int row = idx >> 7;
    int d   = idx & 127;
    int t   = row & (T_ - 1);
    const float* f = feat + (size_t)row * 3;
    float xv = fmaf(f[0], hw[d],
               fmaf(f[1], hw[D_ + d],
               fmaf(f[2], hw[2 * D_ + d], hb[d])));
    d_x[idx] = xv;
    int j2 = d & ~1;
    float ang = (float)t * __expf(-9.210340371976184f * (float)j2 / 128.0f);
    float pe = (d & 1) ? __cosf(ang) : __sinf(ang);
    float oe = xv + pe;
    d_oute[idx] = oe;
    __nv_bfloat16 h, l;
    bf16split(oe, h, l);
    d_oute_h[idx] = h; d_oute_l[idx] = l;
}

// ---------------- attention per (b,n,h) ------------------------------------------
__global__ __launch_bounds__(128)
void attn_kernel()
{
    int blk = blockIdx.x;
    int h   = blk % H_;
    int bn  = blk / H_;
    const float* base = d_qkv + (size_t)bn * T_ * 384;

    __shared__ float Ks[T_][DH_];
    __shared__ float Vs[T_][DH_];
    int tid = threadIdx.x;
    for (int i = tid; i < T_ * DH_; i += 128) {
        int r = i >> 4, c = i & 15;
        Ks[r][c] = base[(size_t)r * 384 + 128 + h * DH_ + c];
        Vs[r][c] = base[(size_t)r * 384 + 256 + h * DH_ + c];
    }
    __syncthreads();

    const float* qrow = base + (size_t)tid * 384 + h * DH_;
    const float scale = 0.25f;
    float qr[DH_];
#pragma unroll
    for (int d = 0; d < DH_; d++) qr[d] = qrow[d] * scale;

    float m = -INFINITY, l = 0.0f;
    float acc[DH_];
#pragma unroll
    for (int d = 0; d < DH_; d++) acc[d] = 0.0f;

    for (int kk = 0; kk < T_; kk++) {
        float sc = 0.0f;
#pragma unroll
        for (int d = 0; d < DH_; d++) sc = fmaf(qr[d], Ks[kk][d], sc);
        float mn = fmaxf(m, sc);
        float corr = __expf(m - mn);
        float p = __expf(sc - mn);
        l = l * corr + p;
#pragma unroll
        for (int d = 0; d < DH_; d++) acc[d] = fmaf(acc[d], corr, p * Vs[kk][d]);
        m = mn;
    }
    float inv = 1.0f / l;
    size_t rowoff = (size_t)bn * T_ * D_ + (size_t)tid * D_ + h * DH_;
#pragma unroll
    for (int d = 0; d < DH_; d += 2) {
        float o0 = acc[d] * inv;
        float o1 = acc[d + 1] * inv;
        *(uint32_t*)(d_oh + rowoff + d) = packsplit_h(o0, o1);
        *(uint32_t*)(d_ol + rowoff + d) = packsplit_l(o0, o1);
    }
}

// ---------------- sdot + zero ----------------------------------------------------
__global__ void sdot_kernel()
{
    int gid = blockIdx.x * blockDim.x + threadIdx.x;
    int warp = gid >> 5;
    int lane = threadIdx.x & 31;
    if (gid < B_ * NN_) d_g[gid] = 0.0f;
    if (gid < 2) d_stats[gid] = 0.0;
    if (warp >= R_) return;
    size_t base = (size_t)warp * D_ + lane * 4;
    float4 w4 = *(const float4*)(d_oute + base);
    float4 x4 = *(const float4*)(d_x + base);
    float dt = w4.x * x4.x + w4.y * x4.y + w4.z * x4.z + w4.w * x4.w;
#pragma unroll
    for (int o = 16; o; o >>= 1) dt += __shfl_xor_sync(0xffffffffu, dt, o);
    if (lane == 0) {
        int b = warp / (NA_ * T_);
        int rem = warp % (NA_ * T_);
        int n = rem / T_;
        int t = rem % T_;
        d_s[b * NN_ + t * NA_ + n] = dt;
    }
}

// ---------------- edge aggregation ----------------------------------------------
__global__ void edge_kernel(const int* __restrict__ ei, const float* __restrict__ ew)
{
    int gid = blockIdx.x * blockDim.x + threadIdx.x;
    if (gid >= B_ * E_) return;
    int b = gid >> 16;
    int e = gid & (E_ - 1);
    const int* eb = ei + ((size_t)b << 17);
    int src = eb[e];
    int dst = eb[E_ + e];
    atomicAdd(&d_g[(b << 13) + dst], ew[((size_t)b << 16) + e] * d_s[(b << 13) + src]);
}

// ---------------- global batchnorm stats -----------------------------------------
__global__ void bnstats_kernel()
{
    double s = 0.0, sq = 0.0;
    for (int i = blockIdx.x * blockDim.x + threadIdx.x; i < B_ * NN_;
         i += gridDim.x * blockDim.x) {
        double v = (double)d_g[i];
        s += v; sq += v * v;
    }
#pragma unroll
    for (int o = 16; o; o >>= 1) {
        s  += __shfl_xor_sync(0xffffffffu, s, o);
        sq += __shfl_xor_sync(0xffffffffu, sq, o);
    }
    if ((threadIdx.x & 31) == 0) {
        atomicAdd(&d_stats[0], s);
        atomicAdd(&d_stats[1], sq);
    }
}

// ---------------- final outer product --------------------------------------------
__global__ void final_kernel(const float* __restrict__ bng, const float* __restrict__ bnb,
                             const float* __restrict__ lw, const float* __restrict__ lb,
                             float* __restrict__ out)
{
    int idx = blockIdx.x * blockDim.x + threadIdx.x;
    if (idx >= R_ * D_) return;
    int d   = idx & 127;
    int row = idx >> 7;
    int t   = row & 127;
    int bn  = row >> 7;
    int b   = bn >> 6;
    int n   = bn & 63;
    double mu  = d_stats[0] * (1.0 / 32768.0);
    double var = d_stats[1] * (1.0 / 32768.0) - mu * mu;
    float inv = rsqrtf((float)var + EPSV);
    float gval = d_g[b * NN_ + t * NA_ + n];
    float ghat = ((gval - (float)mu) * inv) * bng[0] + bnb[0];
    out[idx] = ghat * lw[d] + lb[d];
}

// ---------------- launcher -------------------------------------------------------
extern "C" void kernel_launch(void* const* d_in, const int* in_sizes, int n_in,
                              void* d_out, int out_size)
{
    const float* feat    = (const float*)d_in[0];
    const int*   eindex  = (const int*)  d_in[1];
    const float* eweight = (const float*)d_in[2];
    const float* hist_w  = (const float*)d_in[3];
    const float* hist_b  = (const float*)d_in[4];
    const float* wq      = (const float*)d_in[5];
    const float* bq      = (const float*)d_in[6];
    const float* wk      = (const float*)d_in[7];
    const float* bk      = (const float*)d_in[8];
    const float* wv      = (const float*)d_in[9];
    const float* bv      = (const float*)d_in[10];
    const float* wo      = (const float*)d_in[11];
    const float* bo      = (const float*)d_in[12];
    const float* ln1g    = (const float*)d_in[13];
    const float* ln1b    = (const float*)d_in[14];
    const float* fw1     = (const float*)d_in[15];
    const float* fb1     = (const float*)d_in[16];
    const float* fw2     = (const float*)d_in[17];
    const float* fb2     = (const float*)d_in[18];
    const float* ln2g    = (const float*)d_in[19];
    const float* ln2b    = (const float*)d_in[20];
    const float* bng     = (const float*)d_in[21];
    const float* bnb     = (const float*)d_in[22];
    const float* linw    = (const float*)d_in[23];
    const float* linb    = (const float*)d_in[24];
    float* out = (float*)d_out;

    float* pqkv = nullptr; cudaGetSymbolAddress((void**)&pqkv, d_qkv);
    float* poute = nullptr; cudaGetSymbolAddress((void**)&poute, d_oute);
    float* ph1  = nullptr; cudaGetSymbolAddress((void**)&ph1, d_h1);
    float* pbqkv = nullptr; cudaGetSymbolAddress((void**)&pbqkv, d_bqkv);

    __nv_bfloat16 *poute_h, *poute_l, *poh, *pol, *ph1h, *ph1l, *pffh, *pffl, *pwh, *pwl;
    cudaGetSymbolAddress((void**)&poute_h, d_oute_h);
    cudaGetSymbolAddress((void**)&poute_l, d_oute_l);
    cudaGetSymbolAddress((void**)&poh,  d_oh);
    cudaGetSymbolAddress((void**)&pol,  d_ol);
    cudaGetSymbolAddress((void**)&ph1h, d_h1h);
    cudaGetSymbolAddress((void**)&ph1l, d_h1l);
    cudaGetSymbolAddress((void**)&pffh, d_ffh);
    cudaGetSymbolAddress((void**)&pffl, d_ffl);
    cudaGetSymbolAddress((void**)&pwh,  d_wh);
    cudaGetSymbolAddress((void**)&pwl,  d_wl);

    cudaFuncSetAttribute(split_gemm_kernel,
                         cudaFuncAttributeMaxDynamicSharedMemorySize, GEMM_SMEM);
    cudaFuncSetAttribute(pgemm_kernel,
                         cudaFuncAttributeMaxDynamicSharedMemorySize, PG_SMEM);

    const int TPB = 256;

    // 0. weight split+transpose
    wsplit_sq_kernel<<<(L_ * 4 * 16384 + TPB - 1) / TPB, TPB>>>(wq, wk, wv, wo, bq, bk, bv);
    wsplit_ff_kernel<<<(2 * L_ * 65536 + TPB - 1) / TPB, TPB>>>(fw1, fw2);

    // 1. x + positional encoding
    hist_pe_kernel<<<(R_ * D_ + TPB - 1) / TPB, TPB>>>(feat, hist_w, hist_b);

    // 2. transformer layers
    for (int l = 0; l < L_; l++) {
        const __nv_bfloat16* wqkvh = pwh + l * 49152;
        const __nv_bfloat16* wqkvl = pwl + l * 49152;
        const __nv_bfloat16* woh = pwh + 147456 + l * 16384;
        const __nv_bfloat16* wol = pwl + 147456 + l * 16384;
        const __nv_bfloat16* f1h = pwh + 196608 + l * 65536;
        const __nv_bfloat16* f1l = pwl + 196608 + l * 65536;
        const __nv_bfloat16* f2h = pwh + 393216 + l * 65536;
        const __nv_bfloat16* f2l = pwl + 393216 + l * 65536;

        // fused QKV: N=384, MT=2 -> grid (3, 128)
        pgemm_kernel<<<dim3(3, 128), 256, PG_SMEM>>>(
            poute_h, poute_l, wqkvh, wqkvl, pbqkv + l * 384,
            pqkv, nullptr, nullptr, 384, 0, 0, nullptr, nullptr, nullptr, 2);

        attn_kernel<<<B_ * NA_ * H_, 128>>>();

        // O-proj + residual + LN1 -> h1, MT=1 -> grid (1, 256)
        pgemm_kernel<<<dim3(1, 256), 256, PG_SMEM>>>(
            poh, pol, woh, wol, bo + l * D_,
            ph1, ph1h, ph1l, D_, 0, 1, poute, ln1g + l * D_, ln1b + l * D_, 1);

        // FFN-1 (ReLU), MT=2 -> grid (4, 128)
        pgemm_kernel<<<dim3(4, 128), 256, PG_SMEM>>>(
            ph1h, ph1l, f1h, f1l, fb1 + l * DFF_,
            nullptr, pffh, pffl, DFF_, 1, 0, nullptr, nullptr, nullptr, 2);

        // FFN-2 (K=512) + residual + LN2 -> oute
        split_gemm_kernel<<<dim3(1, 256), 256, GEMM_SMEM>>>(
            pffh, pffl, f2h, f2l, fb2 + l * D_,
            poute, poute_h, poute_l, DFF_, D_, 0, 1, ph1, ln2g + l * D_, ln2b + l * D_);
    }

    // 3. scoring dot products (+ zero of d_g/d_stats)
    sdot_kernel<<<(R_ * 32 + TPB - 1) / TPB, TPB>>>();

    // 4. edge aggregation
    edge_kernel<<<(B_ * E_ + TPB - 1) / TPB, TPB>>>(eindex, eweight);

    // 5. global batchnorm stats + final outer product
    bnstats_kernel<<<64, TPB>>>();
    final_kernel<<<(R_ * D_ + TPB - 1) / TPB, TPB>>>(bng, bnb, linw, linb, out);
}